// round 1
// baseline (speedup 1.0000x reference)
#include <cuda_runtime.h>
#include <math.h>

#define B_   32
#define N_   4096
#define D_   256
#define S_   8
#define H_   512
#define TOK  (B_*N_)      // 131072
#define EPS  1e-5f

// ---------------- scratch (device globals; no runtime allocation) ----------
__device__ float g_k[TOK*D_];        // 128 MB
__device__ float g_v[TOK*D_];        // 128 MB
__device__ float g_mean[TOK];
__device__ float g_rstd[TOK];
__device__ float g_slots[B_*S_*D_];
__device__ float g_q[B_*S_*D_];
__device__ float g_attn[TOK*S_];     // softmax + 1e-8, pre-renorm
__device__ float g_colsum[B_*S_];
__device__ float g_updates[B_*S_*D_];

__device__ __forceinline__ float sigmoidf_(float x) { return 1.f / (1.f + expf(-x)); }

// ---------------- K1: per-token mean/rstd of inputs ------------------------
__global__ void k_meanvar(const float* __restrict__ x) {
    int warp = threadIdx.x >> 5, lane = threadIdx.x & 31;
    int tok = blockIdx.x * 8 + warp;
    const float4* row = (const float4*)(x + (size_t)tok * D_);
    float4 a = row[lane*2], b = row[lane*2+1];
    float s = a.x+a.y+a.z+a.w + b.x+b.y+b.z+b.w;
    float q = a.x*a.x+a.y*a.y+a.z*a.z+a.w*a.w + b.x*b.x+b.y*b.y+b.z*b.z+b.w*b.w;
    #pragma unroll
    for (int o = 16; o; o >>= 1) {
        s += __shfl_xor_sync(0xffffffffu, s, o);
        q += __shfl_xor_sync(0xffffffffu, q, o);
    }
    if (lane == 0) {
        float m = s * (1.f/256.f);
        g_mean[tok] = m;
        g_rstd[tok] = rsqrtf(q * (1.f/256.f) - m*m + EPS);
    }
}

// ---------------- K2: fused LN + K/V projection GEMM -----------------------
// C[131072, 512] = LN(x)[131072,256] @ W^T, cols 0..255 -> k (wk), 256..511 -> v (wv)
__global__ void __launch_bounds__(256) k_kv_gemm(
    const float* __restrict__ x, const float* __restrict__ lng, const float* __restrict__ lnb,
    const float* __restrict__ wk, const float* __restrict__ bk,
    const float* __restrict__ wv, const float* __restrict__ bv)
{
    __shared__ __align__(16) float As[16][128];
    __shared__ __align__(16) float Bs[16][128];
    int tid = threadIdx.x;
    int m0 = blockIdx.y * 128;
    int n0 = blockIdx.x * 128;
    int tx = tid & 15, ty = tid >> 4;

    float acc[8][8];
    #pragma unroll
    for (int i = 0; i < 8; i++)
        #pragma unroll
        for (int j = 0; j < 8; j++) acc[i][j] = 0.f;

    int lr = tid >> 2;          // 0..63
    int lc = (tid & 3) << 2;    // 0,4,8,12

    for (int k0 = 0; k0 < 256; k0 += 16) {
        float4 gv  = *(const float4*)&lng[k0 + lc];
        float4 bv4 = *(const float4*)&lnb[k0 + lc];
        #pragma unroll
        for (int h = 0; h < 2; h++) {
            int m  = lr + h*64;
            int gm = m0 + m;
            float4 xv = *(const float4*)&x[gm*256 + k0 + lc];
            float mn = g_mean[gm], rs = g_rstd[gm];
            As[lc+0][m] = (xv.x - mn)*rs*gv.x + bv4.x;
            As[lc+1][m] = (xv.y - mn)*rs*gv.y + bv4.y;
            As[lc+2][m] = (xv.z - mn)*rs*gv.z + bv4.z;
            As[lc+3][m] = (xv.w - mn)*rs*gv.w + bv4.w;

            int j = n0 + lr + h*64;
            const float* wrow = (j < 256) ? (wk + j*256) : (wv + (j-256)*256);
            float4 wv4 = *(const float4*)&wrow[k0 + lc];
            Bs[lc+0][lr + h*64] = wv4.x;
            Bs[lc+1][lr + h*64] = wv4.y;
            Bs[lc+2][lr + h*64] = wv4.z;
            Bs[lc+3][lr + h*64] = wv4.w;
        }
        __syncthreads();
        #pragma unroll
        for (int kk = 0; kk < 16; kk++) {
            float4 a0 = *(const float4*)&As[kk][ty*8];
            float4 a1 = *(const float4*)&As[kk][ty*8 + 4];
            float4 b0 = *(const float4*)&Bs[kk][tx*8];
            float4 b1 = *(const float4*)&Bs[kk][tx*8 + 4];
            float a[8] = {a0.x,a0.y,a0.z,a0.w,a1.x,a1.y,a1.z,a1.w};
            float b[8] = {b0.x,b0.y,b0.z,b0.w,b1.x,b1.y,b1.z,b1.w};
            #pragma unroll
            for (int i = 0; i < 8; i++)
                #pragma unroll
                for (int j = 0; j < 8; j++)
                    acc[i][j] += a[i]*b[j];
        }
        __syncthreads();
    }

    #pragma unroll
    for (int i = 0; i < 8; i++) {
        int row = m0 + ty*8 + i;
        #pragma unroll
        for (int j = 0; j < 8; j++) {
            int col = n0 + tx*8 + j;
            float c = acc[i][j];
            if (col < 256) g_k[row*256 + col]        = c + bk[col];
            else           g_v[row*256 + (col-256)]  = c + bv[col-256];
        }
    }
}

// ---------------- K3: slots init -------------------------------------------
__global__ void k_init_slots(const float* __restrict__ noise,
                             const float* __restrict__ mu,
                             const float* __restrict__ sigma_raw) {
    int i = blockIdx.x*blockDim.x + threadIdx.x;
    if (i < B_*S_*D_) {
        int d = i & 255;
        float sr = sigma_raw[d];
        float sp = (sr > 20.f) ? sr : log1pf(expf(sr));
        g_slots[i] = mu[d] + sp * noise[i];
    }
}

// ---------------- block stats helper (256 threads, one value each) ---------
__device__ __forceinline__ void block_stats256(float v, float& mean, float& rstd) {
    __shared__ float rs[8], rq[8];
    float s = v, q = v*v;
    #pragma unroll
    for (int o = 16; o; o >>= 1) {
        s += __shfl_xor_sync(0xffffffffu, s, o);
        q += __shfl_xor_sync(0xffffffffu, q, o);
    }
    int w = threadIdx.x >> 5, l = threadIdx.x & 31;
    if (!l) { rs[w] = s; rq[w] = q; }
    __syncthreads();
    float S = 0.f, Q = 0.f;
    #pragma unroll
    for (int i = 0; i < 8; i++) { S += rs[i]; Q += rq[i]; }
    mean = S * (1.f/256.f);
    rstd = rsqrtf(Q * (1.f/256.f) - mean*mean + EPS);
}

// ---------------- K4: q = LN(slots) @ wq^T + bq -----------------------------
__global__ void k_qproj(const float* __restrict__ g, const float* __restrict__ b,
                        const float* __restrict__ wq, const float* __restrict__ bq) {
    __shared__ __align__(16) float sa[D_];
    int row = blockIdx.x;     // b*8+s
    int t = threadIdx.x;
    float v = g_slots[row*D_ + t];
    float m, r;
    block_stats256(v, m, r);
    sa[t] = (v - m)*r*g[t] + b[t];
    __syncthreads();
    float acc = bq[t];
    const float* w = wq + t*D_;
    #pragma unroll 4
    for (int e = 0; e < D_; e += 4) {
        float4 w4 = *(const float4*)&w[e];
        acc += w4.x*sa[e] + w4.y*sa[e+1] + w4.z*sa[e+2] + w4.w*sa[e+3];
    }
    g_q[row*D_ + t] = acc;
}

// ---------------- K5: logits + softmax(+1e-8) + column sums -----------------
// warp-per-token; q held in registers (qr[8][8] per lane)
__global__ void __launch_bounds__(256) k_logits() {
    int b = blockIdx.y, chunk = blockIdx.x;           // chunk 0..15
    int warp = threadIdx.x >> 5, lane = threadIdx.x & 31;

    float qr[8][8];
    const float* qb = g_q + b*S_*D_;
    #pragma unroll
    for (int s = 0; s < 8; s++) {
        float4 a = *(const float4*)&qb[s*256 + lane*8];
        float4 c = *(const float4*)&qb[s*256 + lane*8 + 4];
        qr[s][0]=a.x; qr[s][1]=a.y; qr[s][2]=a.z; qr[s][3]=a.w;
        qr[s][4]=c.x; qr[s][5]=c.y; qr[s][6]=c.z; qr[s][7]=c.w;
    }

    float csum[8] = {0,0,0,0,0,0,0,0};
    for (int t = warp; t < 256; t += 8) {
        int n = chunk*256 + t;
        const float* krow = g_k + ((size_t)(b*N_ + n))*D_ + lane*8;
        float4 a = *(const float4*)krow;
        float4 c = *(const float4*)(krow + 4);
        float kf[8] = {a.x,a.y,a.z,a.w,c.x,c.y,c.z,c.w};

        float lg[8];
        #pragma unroll
        for (int s = 0; s < 8; s++) {
            float p = 0.f;
            #pragma unroll
            for (int j = 0; j < 8; j++) p += kf[j]*qr[s][j];
            #pragma unroll
            for (int o = 16; o; o >>= 1) p += __shfl_xor_sync(0xffffffffu, p, o);
            lg[s] = p * 0.0625f;   // * SLOT_DIM^-0.5
        }
        float mx = lg[0];
        #pragma unroll
        for (int s = 1; s < 8; s++) mx = fmaxf(mx, lg[s]);
        float e[8], sum = 0.f;
        #pragma unroll
        for (int s = 0; s < 8; s++) { e[s] = expf(lg[s]-mx); sum += e[s]; }
        float inv = 1.f/sum;
        float p8[8];
        #pragma unroll
        for (int s = 0; s < 8; s++) p8[s] = e[s]*inv + 1e-8f;

        if (lane == 0) {
            float* dst = g_attn + ((size_t)(b*N_ + n))*8;
            ((float4*)dst)[0] = make_float4(p8[0],p8[1],p8[2],p8[3]);
            ((float4*)dst)[1] = make_float4(p8[4],p8[5],p8[6],p8[7]);
            #pragma unroll
            for (int s = 0; s < 8; s++) csum[s] += p8[s];
        }
    }
    if (lane == 0) {
        #pragma unroll
        for (int s = 0; s < 8; s++) atomicAdd(&g_colsum[b*8 + s], csum[s]);
    }
}

// ---------------- K6: updates[b,s,d] = sum_n attn_raw * v ------------------
__global__ void __launch_bounds__(256) k_updates() {
    int b = blockIdx.y, chunk = blockIdx.x;   // 4 chunks of 1024 tokens
    int d = threadIdx.x;
    float acc[8] = {0,0,0,0,0,0,0,0};
    __shared__ float sA[32][8];
    int tok0 = b*N_ + chunk*1024;
    for (int base = 0; base < 1024; base += 32) {
        int li = threadIdx.x;
        sA[li >> 3][li & 7] = g_attn[(size_t)(tok0 + base + (li >> 3))*8 + (li & 7)];
        __syncthreads();
        #pragma unroll 4
        for (int i = 0; i < 32; i++) {
            float vv = g_v[(size_t)(tok0 + base + i)*D_ + d];
            #pragma unroll
            for (int s = 0; s < 8; s++) acc[s] += sA[i][s]*vv;
        }
        __syncthreads();
    }
    #pragma unroll
    for (int s = 0; s < 8; s++)
        atomicAdd(&g_updates[(b*8 + s)*D_ + d], acc[s]);
}

// ---------------- K7: GRU cell + LN + MLP residual --------------------------
__global__ void __launch_bounds__(256) k_gru_mlp(
    const float* __restrict__ w_ih, const float* __restrict__ w_hh,
    const float* __restrict__ b_ih, const float* __restrict__ b_hh,
    const float* __restrict__ lng,  const float* __restrict__ lnb,
    const float* __restrict__ w1,   const float* __restrict__ b1,
    const float* __restrict__ w2,   const float* __restrict__ b2,
    float* __restrict__ out_slots)
{
    __shared__ __align__(16) float su[D_];
    __shared__ __align__(16) float sh[D_];
    __shared__ __align__(16) float sa[D_];
    __shared__ __align__(16) float sh1[H_];
    int row = blockIdx.x;   // b*8+s
    int t = threadIdx.x;

    float inv_cs = 1.f / g_colsum[row];
    su[t] = g_updates[row*D_ + t] * inv_cs;
    float hprev = g_slots[row*D_ + t];
    sh[t] = hprev;
    __syncthreads();

    float xr = b_ih[t],      xz = b_ih[256 + t], xn = b_ih[512 + t];
    float hr = b_hh[t],      hz = b_hh[256 + t], hn = b_hh[512 + t];
    const float* wir = w_ih + t*D_;
    const float* wiz = w_ih + (256 + t)*D_;
    const float* win = w_ih + (512 + t)*D_;
    const float* whr = w_hh + t*D_;
    const float* whz = w_hh + (256 + t)*D_;
    const float* whn = w_hh + (512 + t)*D_;

    #pragma unroll 4
    for (int e = 0; e < D_; e += 4) {
        float4 u4 = *(const float4*)&su[e];
        float4 h4 = *(const float4*)&sh[e];
        float4 w;
        w = *(const float4*)&wir[e]; xr += w.x*u4.x + w.y*u4.y + w.z*u4.z + w.w*u4.w;
        w = *(const float4*)&wiz[e]; xz += w.x*u4.x + w.y*u4.y + w.z*u4.z + w.w*u4.w;
        w = *(const float4*)&win[e]; xn += w.x*u4.x + w.y*u4.y + w.z*u4.z + w.w*u4.w;
        w = *(const float4*)&whr[e]; hr += w.x*h4.x + w.y*h4.y + w.z*h4.z + w.w*h4.w;
        w = *(const float4*)&whz[e]; hz += w.x*h4.x + w.y*h4.y + w.z*h4.z + w.w*h4.w;
        w = *(const float4*)&whn[e]; hn += w.x*h4.x + w.y*h4.y + w.z*h4.z + w.w*h4.w;
    }
    float r = sigmoidf_(xr + hr);
    float z = sigmoidf_(xz + hz);
    float nn = tanhf(xn + r*hn);
    float hnew = (1.f - z)*nn + z*hprev;

    float m, rs;
    __syncthreads();                 // su/sh no longer needed after this point
    block_stats256(hnew, m, rs);
    sa[t] = (hnew - m)*rs*lng[t] + lnb[t];
    __syncthreads();

    float a1 = b1[t], a2 = b1[t + 256];
    const float* w1a = w1 + t*D_;
    const float* w1b = w1 + (t + 256)*D_;
    #pragma unroll 4
    for (int e = 0; e < D_; e += 4) {
        float4 s4 = *(const float4*)&sa[e];
        float4 wa = *(const float4*)&w1a[e];
        float4 wb = *(const float4*)&w1b[e];
        a1 += wa.x*s4.x + wa.y*s4.y + wa.z*s4.z + wa.w*s4.w;
        a2 += wb.x*s4.x + wb.y*s4.y + wb.z*s4.z + wb.w*s4.w;
    }
    sh1[t]       = fmaxf(a1, 0.f);
    sh1[t + 256] = fmaxf(a2, 0.f);
    __syncthreads();

    float o = b2[t];
    const float* w2r = w2 + t*H_;
    #pragma unroll 4
    for (int e = 0; e < H_; e += 4) {
        float4 h4 = *(const float4*)&sh1[e];
        float4 w4 = *(const float4*)&w2r[e];
        o += w4.x*h4.x + w4.y*h4.y + w4.z*h4.z + w4.w*h4.w;
    }
    float res = hnew + o;
    g_slots[row*D_ + t] = res;
    if (out_slots) out_slots[row*D_ + t] = res;
}

// ---------------- K8: final attn normalize to d_out -------------------------
__global__ void k_attn_out(float* __restrict__ dst) {
    int i = blockIdx.x*blockDim.x + threadIdx.x;
    if (i < TOK*S_) {
        int s = i & 7;
        int b = i >> 15;              // 4096*8 = 2^15 per batch
        dst[i] = g_attn[i] / g_colsum[b*8 + s];
    }
}

// ---------------- zero kernel ----------------------------------------------
__global__ void k_zero() {
    int i = blockIdx.x*blockDim.x + threadIdx.x;
    if (i < B_*S_*D_) g_updates[i] = 0.f;
    if (i < B_*S_)    g_colsum[i]  = 0.f;
}

// ---------------- host ------------------------------------------------------
extern "C" void kernel_launch(void* const* d_in, const int* in_sizes, int n_in,
                              void* d_out, int out_size) {
    const float* inputs     = (const float*)d_in[0];
    const float* init_noise = (const float*)d_in[1];
    const float* mu         = (const float*)d_in[2];
    const float* sigma_raw  = (const float*)d_in[3];
    const float* ln_in_g    = (const float*)d_in[4];
    const float* ln_in_b    = (const float*)d_in[5];
    const float* ln_s_g     = (const float*)d_in[6];
    const float* ln_s_b     = (const float*)d_in[7];
    const float* ln_m_g     = (const float*)d_in[8];
    const float* ln_m_b     = (const float*)d_in[9];
    const float* wq         = (const float*)d_in[10];
    const float* bq         = (const float*)d_in[11];
    const float* wk         = (const float*)d_in[12];
    const float* bk         = (const float*)d_in[13];
    const float* wv         = (const float*)d_in[14];
    const float* bv         = (const float*)d_in[15];
    const float* w_ih       = (const float*)d_in[16];
    const float* w_hh       = (const float*)d_in[17];
    const float* b_ih       = (const float*)d_in[18];
    const float* b_hh       = (const float*)d_in[19];
    const float* w1         = (const float*)d_in[20];
    const float* b1         = (const float*)d_in[21];
    const float* w2         = (const float*)d_in[22];
    const float* b2         = (const float*)d_in[23];
    float* out = (float*)d_out;

    k_meanvar<<<TOK/8, 256>>>(inputs);
    k_kv_gemm<<<dim3(4, TOK/128), 256>>>(inputs, ln_in_g, ln_in_b, wk, bk, wv, bv);
    k_init_slots<<<(B_*S_*D_ + 255)/256, 256>>>(init_noise, mu, sigma_raw);

    for (int it = 0; it < 3; ++it) {
        bool last = (it == 2);
        k_qproj<<<B_*S_, 256>>>(ln_s_g, ln_s_b, wq, bq);
        k_zero<<<(B_*S_*D_ + 255)/256, 256>>>();
        k_logits<<<dim3(16, B_), 256>>>();
        k_updates<<<dim3(4, B_), 256>>>();
        k_gru_mlp<<<B_*S_, 256>>>(w_ih, w_hh, b_ih, b_hh, ln_m_g, ln_m_b,
                                  w1, b1, w2, b2, last ? out : nullptr);
        if (last) k_attn_out<<<(TOK*S_ + 255)/256, 256>>>(out + B_*S_*D_);
    }
}

// round 3
// speedup vs baseline: 1.2614x; 1.2614x over previous
#include <cuda_runtime.h>
#include <cstdint>
#include <math.h>

#define B_   32
#define N_   4096
#define D_   256
#define S_   8
#define H_   512
#define TOK  (B_*N_)      // 131072
#define EPS  1e-5f

// ---------------- scratch (device globals; no runtime allocation) ----------
__device__ float g_k[TOK*D_];        // 128 MB
__device__ float g_v[TOK*D_];        // 128 MB
__device__ float g_mean[TOK];
__device__ float g_rstd[TOK];
__device__ float g_slots[B_*S_*D_];
__device__ float g_q[B_*S_*D_];
__device__ float g_attn[TOK*S_];     // softmax + 1e-8, pre-renorm
__device__ float g_colsum[B_*S_];
__device__ float g_updates[B_*S_*D_];

__device__ __forceinline__ float sigmoidf_(float x) { return 1.f / (1.f + expf(-x)); }

// tf32 mma.sync (baseline PTX ISA, sm_80+; no arch-'a' features)
__device__ __forceinline__ void mma16n8k8(float* c, const uint32_t* a, const uint32_t* b) {
    asm volatile(
        "mma.sync.aligned.m16n8k8.row.col.f32.tf32.tf32.f32 "
        "{%0,%1,%2,%3}, {%4,%5,%6,%7}, {%8,%9}, {%0,%1,%2,%3};"
        : "+f"(c[0]), "+f"(c[1]), "+f"(c[2]), "+f"(c[3])
        : "r"(a[0]), "r"(a[1]), "r"(a[2]), "r"(a[3]), "r"(b[0]), "r"(b[1]));
}
__device__ __forceinline__ float tf32_hi(float x) {
    return __uint_as_float(__float_as_uint(x) & 0xFFFFE000u);
}

// ---------------- K1: per-token mean/rstd of inputs ------------------------
__global__ void k_meanvar(const float* __restrict__ x) {
    int warp = threadIdx.x >> 5, lane = threadIdx.x & 31;
    int tok = blockIdx.x * 8 + warp;
    const float4* row = (const float4*)(x + (size_t)tok * D_);
    float4 a = row[lane*2], b = row[lane*2+1];
    float s = a.x+a.y+a.z+a.w + b.x+b.y+b.z+b.w;
    float q = a.x*a.x+a.y*a.y+a.z*a.z+a.w*a.w + b.x*b.x+b.y*b.y+b.z*b.z+b.w*b.w;
    #pragma unroll
    for (int o = 16; o; o >>= 1) {
        s += __shfl_xor_sync(0xffffffffu, s, o);
        q += __shfl_xor_sync(0xffffffffu, q, o);
    }
    if (lane == 0) {
        float m = s * (1.f/256.f);
        g_mean[tok] = m;
        g_rstd[tok] = rsqrtf(q * (1.f/256.f) - m*m + EPS);
    }
}

// ---------------- K2: tf32 mma.sync 3x-split K/V projection GEMM -----------
// grid = (4, 1024). blockIdx.x: col tile cb. cb 0,1 -> k (wk,bk) cols 0/128;
// cb 2,3 -> v (wv,bv) cols 0/128. Per CTA: C[128,128] = LN(x)[128,256] @ w^T
#define PITCH 20

__global__ void __launch_bounds__(256, 1) k_kv_mma(
    const float* __restrict__ x, const float* __restrict__ lng, const float* __restrict__ lnb,
    const float* __restrict__ wk, const float* __restrict__ bk,
    const float* __restrict__ wv, const float* __restrict__ bv)
{
    __shared__ __align__(16) float sAh[128*PITCH];
    __shared__ __align__(16) float sAl[128*PITCH];
    __shared__ __align__(16) float sBh[128*PITCH];
    __shared__ __align__(16) float sBl[128*PITCH];

    int tid = threadIdx.x;
    int wid = tid >> 5, lane = tid & 31;
    int m0 = blockIdx.y * 128;
    int cb = blockIdx.x;
    const float* w    = (cb < 2) ? wk : wv;
    const float* bias = (cb < 2) ? bk : bv;
    float* outp       = (cb < 2) ? g_k : g_v;
    int colbase = (cb & 1) * 128;

    // loader geometry: 512 float4 chunks for A (128x16), thread handles c=tid, tid+256
    int rA0 = tid >> 2, rA1 = (tid + 256) >> 2;     // rows 0..63, 64..127
    int col4 = (tid & 3) * 4;                        // k-col within stage: 0,4,8,12
    int gm0 = m0 + rA0, gm1 = m0 + rA1;
    float mn0 = g_mean[gm0], rs0 = g_rstd[gm0];
    float mn1 = g_mean[gm1], rs1 = g_rstd[gm1];
    const float* xr0 = x + (size_t)gm0 * 256 + col4;
    const float* xr1 = x + (size_t)gm1 * 256 + col4;
    const float* wr0 = w + (size_t)(colbase + rA0) * 256 + col4;
    const float* wr1 = w + (size_t)(colbase + rA1) * 256 + col4;

    float acc[2][8][4];
    #pragma unroll
    for (int mf = 0; mf < 2; mf++)
        #pragma unroll
        for (int nf = 0; nf < 8; nf++)
            #pragma unroll
            for (int j = 0; j < 4; j++) acc[mf][nf][j] = 0.f;

    int wm = (wid >> 1) * 32;
    int wn = (wid & 1) * 64;
    int g  = lane >> 2, q = lane & 3;

    // prologue prefetch (stage 0)
    float4 pa0 = *(const float4*)(xr0);
    float4 pa1 = *(const float4*)(xr1);
    float4 pb0 = *(const float4*)(wr0);
    float4 pb1 = *(const float4*)(wr1);
    float4 pg  = *(const float4*)(lng + col4);
    float4 pbt = *(const float4*)(lnb + col4);

    for (int s = 0; s < 16; ++s) {
        // ---- store current stage to smem (LN fuse + hi/lo split) ----
        {
            float a0 = (pa0.x - mn0)*rs0*pg.x + pbt.x;
            float a1 = (pa0.y - mn0)*rs0*pg.y + pbt.y;
            float a2 = (pa0.z - mn0)*rs0*pg.z + pbt.z;
            float a3 = (pa0.w - mn0)*rs0*pg.w + pbt.w;
            float h0 = tf32_hi(a0), h1 = tf32_hi(a1), h2 = tf32_hi(a2), h3 = tf32_hi(a3);
            *(float4*)&sAh[rA0*PITCH + col4] = make_float4(h0, h1, h2, h3);
            *(float4*)&sAl[rA0*PITCH + col4] = make_float4(a0-h0, a1-h1, a2-h2, a3-h3);

            float b0f = (pa1.x - mn1)*rs1*pg.x + pbt.x;
            float b1f = (pa1.y - mn1)*rs1*pg.y + pbt.y;
            float b2f = (pa1.z - mn1)*rs1*pg.z + pbt.z;
            float b3f = (pa1.w - mn1)*rs1*pg.w + pbt.w;
            float j0 = tf32_hi(b0f), j1 = tf32_hi(b1f), j2 = tf32_hi(b2f), j3 = tf32_hi(b3f);
            *(float4*)&sAh[rA1*PITCH + col4] = make_float4(j0, j1, j2, j3);
            *(float4*)&sAl[rA1*PITCH + col4] = make_float4(b0f-j0, b1f-j1, b2f-j2, b3f-j3);

            float w0 = pb0.x, w1 = pb0.y, w2 = pb0.z, w3 = pb0.w;
            float k0h = tf32_hi(w0), k1h = tf32_hi(w1), k2h = tf32_hi(w2), k3h = tf32_hi(w3);
            *(float4*)&sBh[rA0*PITCH + col4] = make_float4(k0h, k1h, k2h, k3h);
            *(float4*)&sBl[rA0*PITCH + col4] = make_float4(w0-k0h, w1-k1h, w2-k2h, w3-k3h);

            float u0 = pb1.x, u1 = pb1.y, u2 = pb1.z, u3 = pb1.w;
            float l0 = tf32_hi(u0), l1 = tf32_hi(u1), l2 = tf32_hi(u2), l3 = tf32_hi(u3);
            *(float4*)&sBh[rA1*PITCH + col4] = make_float4(l0, l1, l2, l3);
            *(float4*)&sBl[rA1*PITCH + col4] = make_float4(u0-l0, u1-l1, u2-l2, u3-l3);
        }
        __syncthreads();

        // ---- prefetch next stage ----
        if (s < 15) {
            int k0n = (s + 1) * 16;
            pa0 = *(const float4*)(xr0 + k0n);
            pa1 = *(const float4*)(xr1 + k0n);
            pb0 = *(const float4*)(wr0 + k0n);
            pb1 = *(const float4*)(wr1 + k0n);
            pg  = *(const float4*)(lng + k0n + col4);
            pbt = *(const float4*)(lnb + k0n + col4);
        }

        // ---- compute: 2 k8 steps ----
        #pragma unroll
        for (int k8 = 0; k8 < 16; k8 += 8) {
            uint32_t ah[2][4], al[2][4];
            #pragma unroll
            for (int mf = 0; mf < 2; mf++) {
                int r0 = (wm + mf*16 + g) * PITCH + k8 + q;
                int r1 = r0 + 8 * PITCH;
                ah[mf][0] = __float_as_uint(sAh[r0]);
                ah[mf][1] = __float_as_uint(sAh[r1]);
                ah[mf][2] = __float_as_uint(sAh[r0 + 4]);
                ah[mf][3] = __float_as_uint(sAh[r1 + 4]);
                al[mf][0] = __float_as_uint(sAl[r0]);
                al[mf][1] = __float_as_uint(sAl[r1]);
                al[mf][2] = __float_as_uint(sAl[r0 + 4]);
                al[mf][3] = __float_as_uint(sAl[r1 + 4]);
            }
            #pragma unroll
            for (int nf = 0; nf < 8; nf++) {
                int nb = (wn + nf*8 + g) * PITCH + k8 + q;
                uint32_t bh[2], bl[2];
                bh[0] = __float_as_uint(sBh[nb]);
                bh[1] = __float_as_uint(sBh[nb + 4]);
                bl[0] = __float_as_uint(sBl[nb]);
                bl[1] = __float_as_uint(sBl[nb + 4]);
                #pragma unroll
                for (int mf = 0; mf < 2; mf++) {
                    mma16n8k8(acc[mf][nf], al[mf], bh);
                    mma16n8k8(acc[mf][nf], ah[mf], bl);
                    mma16n8k8(acc[mf][nf], ah[mf], bh);
                }
            }
        }
        __syncthreads();
    }

    // ---- epilogue: bias + store ----
    #pragma unroll
    for (int nf = 0; nf < 8; nf++) {
        int col = colbase + wn + nf*8 + q*2;
        float2 b2 = *(const float2*)&bias[col];
        #pragma unroll
        for (int mf = 0; mf < 2; mf++) {
            int row0 = m0 + wm + mf*16 + g;
            float2 o0 = make_float2(acc[mf][nf][0] + b2.x, acc[mf][nf][1] + b2.y);
            float2 o1 = make_float2(acc[mf][nf][2] + b2.x, acc[mf][nf][3] + b2.y);
            *(float2*)&outp[(size_t)row0 * 256 + col]       = o0;
            *(float2*)&outp[(size_t)(row0 + 8) * 256 + col] = o1;
        }
    }
}

// ---------------- K3: slots init -------------------------------------------
__global__ void k_init_slots(const float* __restrict__ noise,
                             const float* __restrict__ mu,
                             const float* __restrict__ sigma_raw) {
    int i = blockIdx.x*blockDim.x + threadIdx.x;
    if (i < B_*S_*D_) {
        int d = i & 255;
        float sr = sigma_raw[d];
        float sp = (sr > 20.f) ? sr : log1pf(expf(sr));
        g_slots[i] = mu[d] + sp * noise[i];
    }
}

// ---------------- block stats helper (256 threads, one value each) ---------
__device__ __forceinline__ void block_stats256(float v, float& mean, float& rstd) {
    __shared__ float rs[8], rq[8];
    float s = v, q = v*v;
    #pragma unroll
    for (int o = 16; o; o >>= 1) {
        s += __shfl_xor_sync(0xffffffffu, s, o);
        q += __shfl_xor_sync(0xffffffffu, q, o);
    }
    int w = threadIdx.x >> 5, l = threadIdx.x & 31;
    if (!l) { rs[w] = s; rq[w] = q; }
    __syncthreads();
    float S = 0.f, Q = 0.f;
    #pragma unroll
    for (int i = 0; i < 8; i++) { S += rs[i]; Q += rq[i]; }
    mean = S * (1.f/256.f);
    rstd = rsqrtf(Q * (1.f/256.f) - mean*mean + EPS);
}

// ---------------- K4: q = LN(slots) @ wq^T + bq -----------------------------
__global__ void k_qproj(const float* __restrict__ g, const float* __restrict__ b,
                        const float* __restrict__ wq, const float* __restrict__ bq) {
    __shared__ __align__(16) float sa[D_];
    int row = blockIdx.x;     // b*8+s
    int t = threadIdx.x;
    float v = g_slots[row*D_ + t];
    float m, r;
    block_stats256(v, m, r);
    sa[t] = (v - m)*r*g[t] + b[t];
    __syncthreads();
    float acc0 = bq[t], acc1 = 0.f, acc2 = 0.f, acc3 = 0.f;
    const float* w = wq + t*D_;
    #pragma unroll 4
    for (int e = 0; e < D_; e += 8) {
        float4 w4 = *(const float4*)&w[e];
        float4 w5 = *(const float4*)&w[e+4];
        acc0 += w4.x*sa[e]   + w4.y*sa[e+1];
        acc1 += w4.z*sa[e+2] + w4.w*sa[e+3];
        acc2 += w5.x*sa[e+4] + w5.y*sa[e+5];
        acc3 += w5.z*sa[e+6] + w5.w*sa[e+7];
    }
    g_q[row*D_ + t] = (acc0 + acc1) + (acc2 + acc3);
}

// ---------------- K5: logits + softmax(+1e-8) + column sums -----------------
__global__ void __launch_bounds__(256) k_logits() {
    int b = blockIdx.y, chunk = blockIdx.x;           // chunk 0..15
    int warp = threadIdx.x >> 5, lane = threadIdx.x & 31;

    float qr[8][8];
    const float* qb = g_q + b*S_*D_;
    #pragma unroll
    for (int s = 0; s < 8; s++) {
        float4 a = *(const float4*)&qb[s*256 + lane*8];
        float4 c = *(const float4*)&qb[s*256 + lane*8 + 4];
        qr[s][0]=a.x; qr[s][1]=a.y; qr[s][2]=a.z; qr[s][3]=a.w;
        qr[s][4]=c.x; qr[s][5]=c.y; qr[s][6]=c.z; qr[s][7]=c.w;
    }

    float csum[8] = {0,0,0,0,0,0,0,0};
    for (int t = warp; t < 256; t += 8) {
        int n = chunk*256 + t;
        const float* krow = g_k + ((size_t)(b*N_ + n))*D_ + lane*8;
        float4 a = *(const float4*)krow;
        float4 c = *(const float4*)(krow + 4);
        float kf[8] = {a.x,a.y,a.z,a.w,c.x,c.y,c.z,c.w};

        float lg[8];
        #pragma unroll
        for (int s = 0; s < 8; s++) {
            float p = 0.f;
            #pragma unroll
            for (int j = 0; j < 8; j++) p += kf[j]*qr[s][j];
            #pragma unroll
            for (int o = 16; o; o >>= 1) p += __shfl_xor_sync(0xffffffffu, p, o);
            lg[s] = p * 0.0625f;   // * SLOT_DIM^-0.5
        }
        float mx = lg[0];
        #pragma unroll
        for (int s = 1; s < 8; s++) mx = fmaxf(mx, lg[s]);
        float e[8], sum = 0.f;
        #pragma unroll
        for (int s = 0; s < 8; s++) { e[s] = expf(lg[s]-mx); sum += e[s]; }
        float inv = 1.f/sum;
        float p8[8];
        #pragma unroll
        for (int s = 0; s < 8; s++) p8[s] = e[s]*inv + 1e-8f;

        if (lane == 0) {
            float* dst = g_attn + ((size_t)(b*N_ + n))*8;
            ((float4*)dst)[0] = make_float4(p8[0],p8[1],p8[2],p8[3]);
            ((float4*)dst)[1] = make_float4(p8[4],p8[5],p8[6],p8[7]);
            #pragma unroll
            for (int s = 0; s < 8; s++) csum[s] += p8[s];
        }
    }
    if (lane == 0) {
        #pragma unroll
        for (int s = 0; s < 8; s++) atomicAdd(&g_colsum[b*8 + s], csum[s]);
    }
}

// ---------------- K6: updates[b,s,d] = sum_n attn_raw * v ------------------
__global__ void __launch_bounds__(256) k_updates() {
    int b = blockIdx.y, chunk = blockIdx.x;   // 4 chunks of 1024 tokens
    int d = threadIdx.x;
    float acc[8] = {0,0,0,0,0,0,0,0};
    __shared__ float sA[32][8];
    int tok0 = b*N_ + chunk*1024;
    for (int base = 0; base < 1024; base += 32) {
        int li = threadIdx.x;
        sA[li >> 3][li & 7] = g_attn[(size_t)(tok0 + base + (li >> 3))*8 + (li & 7)];
        __syncthreads();
        #pragma unroll 4
        for (int i = 0; i < 32; i++) {
            float vv = g_v[(size_t)(tok0 + base + i)*D_ + d];
            #pragma unroll
            for (int s = 0; s < 8; s++) acc[s] += sA[i][s]*vv;
        }
        __syncthreads();
    }
    #pragma unroll
    for (int s = 0; s < 8; s++)
        atomicAdd(&g_updates[(b*8 + s)*D_ + d], acc[s]);
}

// ---------------- K7: GRU cell + LN + MLP residual --------------------------
__global__ void __launch_bounds__(256) k_gru_mlp(
    const float* __restrict__ w_ih, const float* __restrict__ w_hh,
    const float* __restrict__ b_ih, const float* __restrict__ b_hh,
    const float* __restrict__ lng,  const float* __restrict__ lnb,
    const float* __restrict__ w1,   const float* __restrict__ b1,
    const float* __restrict__ w2,   const float* __restrict__ b2,
    float* __restrict__ out_slots)
{
    __shared__ __align__(16) float su[D_];
    __shared__ __align__(16) float sh[D_];
    __shared__ __align__(16) float sa[D_];
    __shared__ __align__(16) float sh1[H_];
    int row = blockIdx.x;   // b*8+s
    int t = threadIdx.x;

    float inv_cs = 1.f / g_colsum[row];
    su[t] = g_updates[row*D_ + t] * inv_cs;
    float hprev = g_slots[row*D_ + t];
    sh[t] = hprev;
    __syncthreads();

    float xr = b_ih[t],      xz = b_ih[256 + t], xn = b_ih[512 + t];
    float hr = b_hh[t],      hz = b_hh[256 + t], hn = b_hh[512 + t];
    const float* wir = w_ih + t*D_;
    const float* wiz = w_ih + (256 + t)*D_;
    const float* win = w_ih + (512 + t)*D_;
    const float* whr = w_hh + t*D_;
    const float* whz = w_hh + (256 + t)*D_;
    const float* whn = w_hh + (512 + t)*D_;

    #pragma unroll 4
    for (int e = 0; e < D_; e += 4) {
        float4 u4 = *(const float4*)&su[e];
        float4 h4 = *(const float4*)&sh[e];
        float4 w;
        w = *(const float4*)&wir[e]; xr += w.x*u4.x + w.y*u4.y + w.z*u4.z + w.w*u4.w;
        w = *(const float4*)&wiz[e]; xz += w.x*u4.x + w.y*u4.y + w.z*u4.z + w.w*u4.w;
        w = *(const float4*)&win[e]; xn += w.x*u4.x + w.y*u4.y + w.z*u4.z + w.w*u4.w;
        w = *(const float4*)&whr[e]; hr += w.x*h4.x + w.y*h4.y + w.z*h4.z + w.w*h4.w;
        w = *(const float4*)&whz[e]; hz += w.x*h4.x + w.y*h4.y + w.z*h4.z + w.w*h4.w;
        w = *(const float4*)&whn[e]; hn += w.x*h4.x + w.y*h4.y + w.z*h4.z + w.w*h4.w;
    }
    float r = sigmoidf_(xr + hr);
    float z = sigmoidf_(xz + hz);
    float nn = tanhf(xn + r*hn);
    float hnew = (1.f - z)*nn + z*hprev;

    float m, rs;
    __syncthreads();
    block_stats256(hnew, m, rs);
    sa[t] = (hnew - m)*rs*lng[t] + lnb[t];
    __syncthreads();

    float a1 = b1[t], a2 = b1[t + 256];
    const float* w1a = w1 + t*D_;
    const float* w1b = w1 + (t + 256)*D_;
    #pragma unroll 4
    for (int e = 0; e < D_; e += 4) {
        float4 s4 = *(const float4*)&sa[e];
        float4 wa = *(const float4*)&w1a[e];
        float4 wb = *(const float4*)&w1b[e];
        a1 += wa.x*s4.x + wa.y*s4.y + wa.z*s4.z + wa.w*s4.w;
        a2 += wb.x*s4.x + wb.y*s4.y + wb.z*s4.z + wb.w*s4.w;
    }
    sh1[t]       = fmaxf(a1, 0.f);
    sh1[t + 256] = fmaxf(a2, 0.f);
    __syncthreads();

    float o = b2[t];
    const float* w2r = w2 + t*H_;
    #pragma unroll 4
    for (int e = 0; e < H_; e += 4) {
        float4 h4 = *(const float4*)&sh1[e];
        float4 w4 = *(const float4*)&w2r[e];
        o += w4.x*h4.x + w4.y*h4.y + w4.z*h4.z + w4.w*h4.w;
    }
    float res = hnew + o;
    g_slots[row*D_ + t] = res;
    if (out_slots) out_slots[row*D_ + t] = res;
}

// ---------------- K8: final attn normalize to d_out -------------------------
__global__ void k_attn_out(float* __restrict__ dst) {
    int i = blockIdx.x*blockDim.x + threadIdx.x;
    if (i < TOK*S_) {
        int s = i & 7;
        int b = i >> 15;
        dst[i] = g_attn[i] / g_colsum[b*8 + s];
    }
}

// ---------------- zero kernel ----------------------------------------------
__global__ void k_zero() {
    int i = blockIdx.x*blockDim.x + threadIdx.x;
    if (i < B_*S_*D_) g_updates[i] = 0.f;
    if (i < B_*S_)    g_colsum[i]  = 0.f;
}

// ---------------- host ------------------------------------------------------
extern "C" void kernel_launch(void* const* d_in, const int* in_sizes, int n_in,
                              void* d_out, int out_size) {
    const float* inputs     = (const float*)d_in[0];
    const float* init_noise = (const float*)d_in[1];
    const float* mu         = (const float*)d_in[2];
    const float* sigma_raw  = (const float*)d_in[3];
    const float* ln_in_g    = (const float*)d_in[4];
    const float* ln_in_b    = (const float*)d_in[5];
    const float* ln_s_g     = (const float*)d_in[6];
    const float* ln_s_b     = (const float*)d_in[7];
    const float* ln_m_g     = (const float*)d_in[8];
    const float* ln_m_b     = (const float*)d_in[9];
    const float* wq         = (const float*)d_in[10];
    const float* bq         = (const float*)d_in[11];
    const float* wk         = (const float*)d_in[12];
    const float* bk         = (const float*)d_in[13];
    const float* wv         = (const float*)d_in[14];
    const float* bv         = (const float*)d_in[15];
    const float* w_ih       = (const float*)d_in[16];
    const float* w_hh       = (const float*)d_in[17];
    const float* b_ih       = (const float*)d_in[18];
    const float* b_hh       = (const float*)d_in[19];
    const float* w1         = (const float*)d_in[20];
    const float* b1         = (const float*)d_in[21];
    const float* w2         = (const float*)d_in[22];
    const float* b2         = (const float*)d_in[23];
    float* out = (float*)d_out;

    k_meanvar<<<TOK/8, 256>>>(inputs);
    k_kv_mma<<<dim3(4, TOK/128), 256>>>(inputs, ln_in_g, ln_in_b, wk, bk, wv, bv);
    k_init_slots<<<(B_*S_*D_ + 255)/256, 256>>>(init_noise, mu, sigma_raw);

    for (int it = 0; it < 3; ++it) {
        bool last = (it == 2);
        k_qproj<<<B_*S_, 256>>>(ln_s_g, ln_s_b, wq, bq);
        k_zero<<<(B_*S_*D_ + 255)/256, 256>>>();
        k_logits<<<dim3(16, B_), 256>>>();
        k_updates<<<dim3(4, B_), 256>>>();
        k_gru_mlp<<<B_*S_, 256>>>(w_ih, w_hh, b_ih, b_hh, ln_m_g, ln_m_b,
                                  w1, b1, w2, b2, last ? out : nullptr);
        if (last) k_attn_out<<<(TOK*S_ + 255)/256, 256>>>(out + B_*S_*D_);
    }
}

// round 4
// speedup vs baseline: 1.5714x; 1.2458x over previous
#include <cuda_runtime.h>
#include <cstdint>
#include <math.h>

#define B_   32
#define N_   4096
#define D_   256
#define S_   8
#define H_   512
#define TOK  (B_*N_)      // 131072
#define EPS  1e-5f

// ---------------- scratch (device globals; no runtime allocation) ----------
__device__ float g_k[TOK*D_];        // 128 MB
__device__ float g_v[TOK*D_];        // 128 MB
__device__ float g_mean[TOK];
__device__ float g_rstd[TOK];
__device__ float g_slots[B_*S_*D_];
__device__ float g_q[B_*S_*D_];
__device__ float g_attn[TOK*S_];     // softmax + 1e-8, pre-renorm
__device__ float g_colsum[B_*S_];
__device__ float g_updates[B_*S_*D_];
__device__ float g_wg[512*256];      // g (ln_in_g) ∘ [wk; wv]
__device__ float g_sg[512];          // row sums of g_wg
__device__ float g_sb[512];          // [wk; wv] @ ln_in_b

__device__ __forceinline__ float sigmoidf_(float x) { return 1.f / (1.f + expf(-x)); }

// tf32 mma.sync (baseline PTX ISA, sm_80+; no arch-'a' features)
__device__ __forceinline__ void mma16n8k8(float* c, const uint32_t* a, const uint32_t* b) {
    asm volatile(
        "mma.sync.aligned.m16n8k8.row.col.f32.tf32.tf32.f32 "
        "{%0,%1,%2,%3}, {%4,%5,%6,%7}, {%8,%9}, {%0,%1,%2,%3};"
        : "+f"(c[0]), "+f"(c[1]), "+f"(c[2]), "+f"(c[3])
        : "r"(a[0]), "r"(a[1]), "r"(a[2]), "r"(a[3]), "r"(b[0]), "r"(b[1]));
}
__device__ __forceinline__ void split_tf32(float f, uint32_t& hi, uint32_t& lo) {
    hi = __float_as_uint(f) & 0xFFFFE000u;
    lo = __float_as_uint(f - __uint_as_float(hi));
}
__device__ __forceinline__ uint32_t smem_u32(const void* p) {
    uint32_t a;
    asm("{ .reg .u64 t; cvta.to.shared.u64 t, %1; cvt.u32.u64 %0, t; }" : "=r"(a) : "l"(p));
    return a;
}
__device__ __forceinline__ void cp16(uint32_t dst, const void* src) {
    asm volatile("cp.async.cg.shared.global [%0], [%1], 16;" :: "r"(dst), "l"(src));
}
#define CP_COMMIT() asm volatile("cp.async.commit_group;" ::: "memory")
#define CP_WAIT(n)  asm volatile("cp.async.wait_group %0;" :: "n"(n) : "memory")

// ---------------- K0: prep Wg, sg, sb ---------------------------------------
__global__ void k_prep(const float* __restrict__ wk, const float* __restrict__ wv,
                       const float* __restrict__ lng, const float* __restrict__ lnb) {
    int j = blockIdx.x * 8 + (threadIdx.x >> 5);
    int lane = threadIdx.x & 31;
    const float* wr = (j < 256) ? (wk + (size_t)j*256) : (wv + (size_t)(j-256)*256);
    float4 wa = *(const float4*)&wr[lane*8];
    float4 wb = *(const float4*)&wr[lane*8+4];
    float4 ga = *(const float4*)&lng[lane*8];
    float4 gb = *(const float4*)&lng[lane*8+4];
    float4 ba = *(const float4*)&lnb[lane*8];
    float4 bb = *(const float4*)&lnb[lane*8+4];
    float4 oa = make_float4(wa.x*ga.x, wa.y*ga.y, wa.z*ga.z, wa.w*ga.w);
    float4 ob = make_float4(wb.x*gb.x, wb.y*gb.y, wb.z*gb.z, wb.w*gb.w);
    *(float4*)&g_wg[(size_t)j*256 + lane*8]     = oa;
    *(float4*)&g_wg[(size_t)j*256 + lane*8 + 4] = ob;
    float ssg = oa.x+oa.y+oa.z+oa.w + ob.x+ob.y+ob.z+ob.w;
    float ssb = wa.x*ba.x+wa.y*ba.y+wa.z*ba.z+wa.w*ba.w
              + wb.x*bb.x+wb.y*bb.y+wb.z*bb.z+wb.w*bb.w;
    #pragma unroll
    for (int o = 16; o; o >>= 1) {
        ssg += __shfl_xor_sync(0xffffffffu, ssg, o);
        ssb += __shfl_xor_sync(0xffffffffu, ssb, o);
    }
    if (lane == 0) { g_sg[j] = ssg; g_sb[j] = ssb; }
}

// ---------------- K1: per-token mean/rstd of inputs ------------------------
__global__ void k_meanvar(const float* __restrict__ x) {
    int warp = threadIdx.x >> 5, lane = threadIdx.x & 31;
    int tok = blockIdx.x * 8 + warp;
    const float4* row = (const float4*)(x + (size_t)tok * D_);
    float4 a = row[lane*2], b = row[lane*2+1];
    float s = a.x+a.y+a.z+a.w + b.x+b.y+b.z+b.w;
    float q = a.x*a.x+a.y*a.y+a.z*a.z+a.w*a.w + b.x*b.x+b.y*b.y+b.z*b.z+b.w*b.w;
    #pragma unroll
    for (int o = 16; o; o >>= 1) {
        s += __shfl_xor_sync(0xffffffffu, s, o);
        q += __shfl_xor_sync(0xffffffffu, q, o);
    }
    if (lane == 0) {
        float m = s * (1.f/256.f);
        g_mean[tok] = m;
        g_rstd[tok] = rsqrtf(q * (1.f/256.f) - m*m + EPS);
    }
}

// ---------------- K2: pipelined tf32 3x-split K/V projection GEMM ----------
// grid = (4, 1024). cb: 0 -> k cols 0-127, 1 -> k cols 128-255,
//                       2 -> v cols 0-127, 3 -> v cols 128-255.
// GEMM on RAW x against Wg; LN applied via epilogue affine:
// out = r*acc - (m*r)*sg + sb + bias
#define PITCH 20
#define KS 16

__global__ void __launch_bounds__(256) k_kv_mma2(
    const float* __restrict__ x, const float* __restrict__ bk, const float* __restrict__ bv)
{
    __shared__ __align__(16) float sA[2*128*PITCH];
    __shared__ __align__(16) float sB[2*128*PITCH];

    int tid = threadIdx.x;
    int wid = tid >> 5, lane = tid & 31;
    int m0 = blockIdx.y * 128;
    int cb = blockIdx.x;
    const float* bias = (cb < 2) ? bk : bv;
    float* outp       = (cb < 2) ? g_k : g_v;
    int colbase = (cb & 1) * 128;
    int jbase   = cb * 128;

    // loader geometry: 512 chunks per array, thread handles c = tid, tid+256
    int rA0 = tid >> 2,          kc0 = (tid & 3) * 4;
    int rA1 = (tid + 256) >> 2,  kc1 = kc0;
    const float* xs0 = x + (size_t)(m0 + rA0) * 256 + kc0;
    const float* xs1 = x + (size_t)(m0 + rA1) * 256 + kc1;
    const float* ws0 = g_wg + (size_t)(jbase + rA0) * 256 + kc0;
    const float* ws1 = g_wg + (size_t)(jbase + rA1) * 256 + kc1;

    uint32_t aB = smem_u32(sA), bB = smem_u32(sB);
    uint32_t dA0 = aB + (rA0*PITCH + kc0)*4;
    uint32_t dA1 = aB + (rA1*PITCH + kc1)*4;
    uint32_t dB0 = bB + (rA0*PITCH + kc0)*4;
    uint32_t dB1 = bB + (rA1*PITCH + kc1)*4;
    const uint32_t BUF = 128*PITCH*4;

    float acc[2][8][4];
    #pragma unroll
    for (int mf = 0; mf < 2; mf++)
        #pragma unroll
        for (int nf = 0; nf < 8; nf++)
            #pragma unroll
            for (int j = 0; j < 4; j++) acc[mf][nf][j] = 0.f;

    int wm = (wid >> 1) * 32;
    int wn = (wid & 1) * 64;
    int g  = lane >> 2, q = lane & 3;

    // prologue: stage 0
    cp16(dA0, xs0); cp16(dA1, xs1);
    cp16(dB0, ws0); cp16(dB1, ws1);
    CP_COMMIT();

    for (int s = 0; s < 16; ++s) {
        int buf = s & 1;
        if (s < 15) {
            int nb = (s + 1) & 1;
            int k0 = (s + 1) * KS;
            cp16(dA0 + nb*BUF, xs0 + k0); cp16(dA1 + nb*BUF, xs1 + k0);
            cp16(dB0 + nb*BUF, ws0 + k0); cp16(dB1 + nb*BUF, ws1 + k0);
            CP_COMMIT();
            CP_WAIT(1);
        } else {
            CP_WAIT(0);
        }
        __syncthreads();

        const float* A = sA + buf*128*PITCH;
        const float* Bt = sB + buf*128*PITCH;
        #pragma unroll
        for (int k8 = 0; k8 < KS; k8 += 8) {
            uint32_t ah[2][4], al[2][4];
            #pragma unroll
            for (int mf = 0; mf < 2; mf++) {
                int r0 = (wm + mf*16 + g) * PITCH + k8 + q;
                split_tf32(A[r0],             ah[mf][0], al[mf][0]);
                split_tf32(A[r0 + 8*PITCH],   ah[mf][1], al[mf][1]);
                split_tf32(A[r0 + 4],         ah[mf][2], al[mf][2]);
                split_tf32(A[r0 + 8*PITCH+4], ah[mf][3], al[mf][3]);
            }
            #pragma unroll
            for (int nf = 0; nf < 8; nf++) {
                int nb = (wn + nf*8 + g) * PITCH + k8 + q;
                uint32_t bh[2], bl[2];
                split_tf32(Bt[nb],     bh[0], bl[0]);
                split_tf32(Bt[nb + 4], bh[1], bl[1]);
                #pragma unroll
                for (int mf = 0; mf < 2; mf++) {
                    mma16n8k8(acc[mf][nf], al[mf], bh);
                    mma16n8k8(acc[mf][nf], ah[mf], bl);
                    mma16n8k8(acc[mf][nf], ah[mf], bh);
                }
            }
        }
        __syncthreads();
    }

    // ---- epilogue: LN affine + bias + store ----
    float rr[2][2], mr[2][2];
    #pragma unroll
    for (int mf = 0; mf < 2; mf++) {
        int r0 = m0 + wm + mf*16 + g;
        rr[mf][0] = g_rstd[r0];     mr[mf][0] = g_mean[r0]   * rr[mf][0];
        rr[mf][1] = g_rstd[r0+8];   mr[mf][1] = g_mean[r0+8] * rr[mf][1];
    }
    #pragma unroll
    for (int nf = 0; nf < 8; nf++) {
        int cl = wn + nf*8 + q*2;           // local col 0..127
        int j  = jbase + cl;
        float2 sg2 = make_float2(g_sg[j], g_sg[j+1]);
        float2 cc  = make_float2(g_sb[j]   + bias[colbase + cl],
                                 g_sb[j+1] + bias[colbase + cl + 1]);
        #pragma unroll
        for (int mf = 0; mf < 2; mf++) {
            int r0 = m0 + wm + mf*16 + g;
            float2 o0, o1;
            o0.x = rr[mf][0]*acc[mf][nf][0] - mr[mf][0]*sg2.x + cc.x;
            o0.y = rr[mf][0]*acc[mf][nf][1] - mr[mf][0]*sg2.y + cc.y;
            o1.x = rr[mf][1]*acc[mf][nf][2] - mr[mf][1]*sg2.x + cc.x;
            o1.y = rr[mf][1]*acc[mf][nf][3] - mr[mf][1]*sg2.y + cc.y;
            *(float2*)&outp[(size_t)r0 * 256 + colbase + cl]       = o0;
            *(float2*)&outp[(size_t)(r0+8) * 256 + colbase + cl]   = o1;
        }
    }
}

// ---------------- K3: slots init -------------------------------------------
__global__ void k_init_slots(const float* __restrict__ noise,
                             const float* __restrict__ mu,
                             const float* __restrict__ sigma_raw) {
    int i = blockIdx.x*blockDim.x + threadIdx.x;
    if (i < B_*S_*D_) {
        int d = i & 255;
        float sr = sigma_raw[d];
        float sp = (sr > 20.f) ? sr : log1pf(expf(sr));
        g_slots[i] = mu[d] + sp * noise[i];
    }
}

// ---------------- K4: q = LN(slots) @ wq^T + bq, block per batch ------------
// Also zeroes g_updates / g_colsum for this iteration.
__global__ void __launch_bounds__(256) k_qproj2(
    const float* __restrict__ g, const float* __restrict__ bln,
    const float* __restrict__ wq, const float* __restrict__ bq)
{
    __shared__ __align__(16) float ssl[8][256];
    __shared__ __align__(16) float sa[8][256];
    __shared__ float sm[8], sr[8];
    int b = blockIdx.x, t = threadIdx.x;
    #pragma unroll
    for (int s = 0; s < 8; s++) {
        ssl[s][t] = g_slots[(b*8+s)*256 + t];
        g_updates[(b*8+s)*256 + t] = 0.f;
    }
    if (t < 8) g_colsum[b*8 + t] = 0.f;
    __syncthreads();
    int w = t >> 5, lane = t & 31;
    {
        float s1 = 0.f, s2 = 0.f;
        #pragma unroll
        for (int e = 0; e < 8; e++) {
            float v = ssl[w][lane + e*32];
            s1 += v; s2 += v*v;
        }
        #pragma unroll
        for (int o = 16; o; o >>= 1) {
            s1 += __shfl_xor_sync(0xffffffffu, s1, o);
            s2 += __shfl_xor_sync(0xffffffffu, s2, o);
        }
        if (lane == 0) {
            float m = s1 * (1.f/256.f);
            sm[w] = m;
            sr[w] = rsqrtf(s2 * (1.f/256.f) - m*m + EPS);
        }
    }
    __syncthreads();
    float gt = g[t], bt = bln[t];
    #pragma unroll
    for (int s = 0; s < 8; s++)
        sa[s][t] = (ssl[s][t] - sm[s]) * sr[s] * gt + bt;
    __syncthreads();

    float acc[8] = {0,0,0,0,0,0,0,0};
    const float* wr = wq + (size_t)t * 256;
    #pragma unroll 2
    for (int e = 0; e < 256; e += 4) {
        float4 w4 = *(const float4*)&wr[e];
        #pragma unroll
        for (int s = 0; s < 8; s++) {
            float4 a4 = *(const float4*)&sa[s][e];
            acc[s] += w4.x*a4.x + w4.y*a4.y + w4.z*a4.z + w4.w*a4.w;
        }
    }
    float bqt = bq[t];
    #pragma unroll
    for (int s = 0; s < 8; s++)
        g_q[(b*8+s)*256 + t] = acc[s] + bqt;
}

// ---------------- K5: logits + softmax(+1e-8) + column sums -----------------
__global__ void __launch_bounds__(256) k_logits() {
    int b = blockIdx.y, chunk = blockIdx.x;           // chunk 0..15
    int warp = threadIdx.x >> 5, lane = threadIdx.x & 31;

    float qr[8][8];
    const float* qb = g_q + b*S_*D_;
    #pragma unroll
    for (int s = 0; s < 8; s++) {
        float4 a = *(const float4*)&qb[s*256 + lane*8];
        float4 c = *(const float4*)&qb[s*256 + lane*8 + 4];
        qr[s][0]=a.x; qr[s][1]=a.y; qr[s][2]=a.z; qr[s][3]=a.w;
        qr[s][4]=c.x; qr[s][5]=c.y; qr[s][6]=c.z; qr[s][7]=c.w;
    }

    float csum[8] = {0,0,0,0,0,0,0,0};
    for (int t = warp; t < 256; t += 8) {
        int n = chunk*256 + t;
        const float* krow = g_k + ((size_t)(b*N_ + n))*D_ + lane*8;
        float4 a = *(const float4*)krow;
        float4 c = *(const float4*)(krow + 4);
        float kf[8] = {a.x,a.y,a.z,a.w,c.x,c.y,c.z,c.w};

        float lg[8];
        #pragma unroll
        for (int s = 0; s < 8; s++) {
            float p = 0.f;
            #pragma unroll
            for (int j = 0; j < 8; j++) p += kf[j]*qr[s][j];
            #pragma unroll
            for (int o = 16; o; o >>= 1) p += __shfl_xor_sync(0xffffffffu, p, o);
            lg[s] = p * 0.0625f;   // * SLOT_DIM^-0.5
        }
        float mx = lg[0];
        #pragma unroll
        for (int s = 1; s < 8; s++) mx = fmaxf(mx, lg[s]);
        float e[8], sum = 0.f;
        #pragma unroll
        for (int s = 0; s < 8; s++) { e[s] = expf(lg[s]-mx); sum += e[s]; }
        float inv = 1.f/sum;
        float p8[8];
        #pragma unroll
        for (int s = 0; s < 8; s++) p8[s] = e[s]*inv + 1e-8f;

        if (lane == 0) {
            float* dst = g_attn + ((size_t)(b*N_ + n))*8;
            ((float4*)dst)[0] = make_float4(p8[0],p8[1],p8[2],p8[3]);
            ((float4*)dst)[1] = make_float4(p8[4],p8[5],p8[6],p8[7]);
            #pragma unroll
            for (int s = 0; s < 8; s++) csum[s] += p8[s];
        }
    }
    if (lane == 0) {
        #pragma unroll
        for (int s = 0; s < 8; s++) atomicAdd(&g_colsum[b*8 + s], csum[s]);
    }
}

// ---------------- K6: updates[b,s,d] = sum_n attn_raw * v ------------------
__global__ void __launch_bounds__(256) k_updates() {
    int b = blockIdx.y, chunk = blockIdx.x;   // 4 chunks of 1024 tokens
    int d = threadIdx.x;
    float acc[8] = {0,0,0,0,0,0,0,0};
    __shared__ float sA[32][8];
    int tok0 = b*N_ + chunk*1024;
    for (int base = 0; base < 1024; base += 32) {
        int li = threadIdx.x;
        sA[li >> 3][li & 7] = g_attn[(size_t)(tok0 + base + (li >> 3))*8 + (li & 7)];
        __syncthreads();
        #pragma unroll 4
        for (int i = 0; i < 32; i++) {
            float vv = g_v[(size_t)(tok0 + base + i)*D_ + d];
            #pragma unroll
            for (int s = 0; s < 8; s++) acc[s] += sA[i][s]*vv;
        }
        __syncthreads();
    }
    #pragma unroll
    for (int s = 0; s < 8; s++)
        atomicAdd(&g_updates[(b*8 + s)*D_ + d], acc[s]);
}

// ---------------- K7: GRU + LN + MLP, block per (batch, slot-pair) ---------
__global__ void __launch_bounds__(256) k_gru2(
    const float* __restrict__ w_ih, const float* __restrict__ w_hh,
    const float* __restrict__ b_ih, const float* __restrict__ b_hh,
    const float* __restrict__ lng,  const float* __restrict__ lnb,
    const float* __restrict__ w1,   const float* __restrict__ b1,
    const float* __restrict__ w2,   const float* __restrict__ b2,
    float* __restrict__ out_slots)
{
    __shared__ __align__(16) float su[2][256];
    __shared__ __align__(16) float sh[2][256];
    __shared__ __align__(16) float sa[2][256];
    __shared__ __align__(16) float sh1[2][512];
    __shared__ float sm[2], sr2[2];

    int b = blockIdx.x >> 2;
    int p = blockIdx.x & 3;
    int row0 = b*8 + p*2;
    int t = threadIdx.x;

    #pragma unroll
    for (int sl = 0; sl < 2; sl++) {
        float ics = 1.f / g_colsum[row0 + sl];
        su[sl][t] = g_updates[(row0+sl)*256 + t] * ics;
        sh[sl][t] = g_slots[(row0+sl)*256 + t];
    }
    __syncthreads();

    float xr[2], xz[2], xn[2], hr[2], hz[2], hn[2];
    #pragma unroll
    for (int sl = 0; sl < 2; sl++) {
        xr[sl] = b_ih[t]; xz[sl] = b_ih[256+t]; xn[sl] = b_ih[512+t];
        hr[sl] = b_hh[t]; hz[sl] = b_hh[256+t]; hn[sl] = b_hh[512+t];
    }
    const float* wir = w_ih + (size_t)t*256;
    const float* wiz = w_ih + (size_t)(256+t)*256;
    const float* win = w_ih + (size_t)(512+t)*256;
    const float* whr = w_hh + (size_t)t*256;
    const float* whz = w_hh + (size_t)(256+t)*256;
    const float* whn = w_hh + (size_t)(512+t)*256;

    #pragma unroll 2
    for (int e = 0; e < 256; e += 4) {
        float4 wr4 = *(const float4*)&wir[e];
        float4 wz4 = *(const float4*)&wiz[e];
        float4 wn4 = *(const float4*)&win[e];
        float4 vr4 = *(const float4*)&whr[e];
        float4 vz4 = *(const float4*)&whz[e];
        float4 vn4 = *(const float4*)&whn[e];
        #pragma unroll
        for (int sl = 0; sl < 2; sl++) {
            float4 u4 = *(const float4*)&su[sl][e];
            float4 h4 = *(const float4*)&sh[sl][e];
            xr[sl] += wr4.x*u4.x + wr4.y*u4.y + wr4.z*u4.z + wr4.w*u4.w;
            xz[sl] += wz4.x*u4.x + wz4.y*u4.y + wz4.z*u4.z + wz4.w*u4.w;
            xn[sl] += wn4.x*u4.x + wn4.y*u4.y + wn4.z*u4.z + wn4.w*u4.w;
            hr[sl] += vr4.x*h4.x + vr4.y*h4.y + vr4.z*h4.z + vr4.w*h4.w;
            hz[sl] += vz4.x*h4.x + vz4.y*h4.y + vz4.z*h4.z + vz4.w*h4.w;
            hn[sl] += vn4.x*h4.x + vn4.y*h4.y + vn4.z*h4.z + vn4.w*h4.w;
        }
    }
    float hnew[2];
    #pragma unroll
    for (int sl = 0; sl < 2; sl++) {
        float r = sigmoidf_(xr[sl] + hr[sl]);
        float z = sigmoidf_(xz[sl] + hz[sl]);
        float nn = tanhf(xn[sl] + r*hn[sl]);
        hnew[sl] = (1.f - z)*nn + z*sh[sl][t];
    }
    __syncthreads();
    su[0][t] = hnew[0]; su[1][t] = hnew[1];
    __syncthreads();
    int w = t >> 5, lane = t & 31;
    if (w < 2) {
        float s1 = 0.f, s2 = 0.f;
        #pragma unroll
        for (int e = 0; e < 8; e++) {
            float v = su[w][lane + e*32];
            s1 += v; s2 += v*v;
        }
        #pragma unroll
        for (int o = 16; o; o >>= 1) {
            s1 += __shfl_xor_sync(0xffffffffu, s1, o);
            s2 += __shfl_xor_sync(0xffffffffu, s2, o);
        }
        if (lane == 0) {
            float m = s1 * (1.f/256.f);
            sm[w] = m;
            sr2[w] = rsqrtf(s2 * (1.f/256.f) - m*m + EPS);
        }
    }
    __syncthreads();
    float gt = lng[t], bt = lnb[t];
    sa[0][t] = (hnew[0] - sm[0]) * sr2[0] * gt + bt;
    sa[1][t] = (hnew[1] - sm[1]) * sr2[1] * gt + bt;
    __syncthreads();

    // MLP layer 1: rows t and t+256
    float a1[2] = {b1[t], b1[t]};
    float a2[2] = {b1[256+t], b1[256+t]};
    const float* w1a = w1 + (size_t)t*256;
    const float* w1b = w1 + (size_t)(256+t)*256;
    #pragma unroll 2
    for (int e = 0; e < 256; e += 4) {
        float4 wa = *(const float4*)&w1a[e];
        float4 wb = *(const float4*)&w1b[e];
        #pragma unroll
        for (int sl = 0; sl < 2; sl++) {
            float4 s4 = *(const float4*)&sa[sl][e];
            a1[sl] += wa.x*s4.x + wa.y*s4.y + wa.z*s4.z + wa.w*s4.w;
            a2[sl] += wb.x*s4.x + wb.y*s4.y + wb.z*s4.z + wb.w*s4.w;
        }
    }
    sh1[0][t] = fmaxf(a1[0], 0.f); sh1[0][256+t] = fmaxf(a2[0], 0.f);
    sh1[1][t] = fmaxf(a1[1], 0.f); sh1[1][256+t] = fmaxf(a2[1], 0.f);
    __syncthreads();

    float o[2] = {b2[t], b2[t]};
    const float* w2r = w2 + (size_t)t*512;
    #pragma unroll 2
    for (int e = 0; e < 512; e += 4) {
        float4 w4 = *(const float4*)&w2r[e];
        #pragma unroll
        for (int sl = 0; sl < 2; sl++) {
            float4 h4 = *(const float4*)&sh1[sl][e];
            o[sl] += w4.x*h4.x + w4.y*h4.y + w4.z*h4.z + w4.w*h4.w;
        }
    }
    #pragma unroll
    for (int sl = 0; sl < 2; sl++) {
        float res = hnew[sl] + o[sl];
        g_slots[(row0+sl)*256 + t] = res;
        if (out_slots) out_slots[(row0+sl)*256 + t] = res;
    }
}

// ---------------- K8: final attn normalize to d_out -------------------------
__global__ void k_attn_out(float* __restrict__ dst) {
    int i = blockIdx.x*blockDim.x + threadIdx.x;
    if (i < TOK*S_) {
        int s = i & 7;
        int b = i >> 15;
        dst[i] = g_attn[i] / g_colsum[b*8 + s];
    }
}

// ---------------- host ------------------------------------------------------
extern "C" void kernel_launch(void* const* d_in, const int* in_sizes, int n_in,
                              void* d_out, int out_size) {
    const float* inputs     = (const float*)d_in[0];
    const float* init_noise = (const float*)d_in[1];
    const float* mu         = (const float*)d_in[2];
    const float* sigma_raw  = (const float*)d_in[3];
    const float* ln_in_g    = (const float*)d_in[4];
    const float* ln_in_b    = (const float*)d_in[5];
    const float* ln_s_g     = (const float*)d_in[6];
    const float* ln_s_b     = (const float*)d_in[7];
    const float* ln_m_g     = (const float*)d_in[8];
    const float* ln_m_b     = (const float*)d_in[9];
    const float* wq         = (const float*)d_in[10];
    const float* bq         = (const float*)d_in[11];
    const float* wk         = (const float*)d_in[12];
    const float* bk         = (const float*)d_in[13];
    const float* wv         = (const float*)d_in[14];
    const float* bv         = (const float*)d_in[15];
    const float* w_ih       = (const float*)d_in[16];
    const float* w_hh       = (const float*)d_in[17];
    const float* b_ih       = (const float*)d_in[18];
    const float* b_hh       = (const float*)d_in[19];
    const float* w1         = (const float*)d_in[20];
    const float* b1         = (const float*)d_in[21];
    const float* w2         = (const float*)d_in[22];
    const float* b2         = (const float*)d_in[23];
    float* out = (float*)d_out;

    k_prep<<<64, 256>>>(wk, wv, ln_in_g, ln_in_b);
    k_meanvar<<<TOK/8, 256>>>(inputs);
    k_kv_mma2<<<dim3(4, TOK/128), 256>>>(inputs, bk, bv);
    k_init_slots<<<(B_*S_*D_ + 255)/256, 256>>>(init_noise, mu, sigma_raw);

    for (int it = 0; it < 3; ++it) {
        bool last = (it == 2);
        k_qproj2<<<B_, 256>>>(ln_s_g, ln_s_b, wq, bq);
        k_logits<<<dim3(16, B_), 256>>>();
        k_updates<<<dim3(4, B_), 256>>>();
        k_gru2<<<B_*4, 256>>>(w_ih, w_hh, b_ih, b_hh, ln_m_g, ln_m_b,
                              w1, b1, w2, b2, last ? out : nullptr);
        if (last) k_attn_out<<<(TOK*S_ + 255)/256, 256>>>(out + B_*S_*D_);
    }
}

// round 5
// speedup vs baseline: 1.7358x; 1.1046x over previous
#include <cuda_runtime.h>
#include <cuda_bf16.h>
#include <cstdint>
#include <math.h>

#define B_   32
#define N_   4096
#define D_   256
#define S_   8
#define H_   512
#define TOK  (B_*N_)      // 131072
#define EPS  1e-5f

// ---------------- scratch (device globals; no runtime allocation) ----------
__device__ float g_k[TOK*D_];        // 128 MB
__device__ float g_v[TOK*D_];        // 128 MB
__device__ float g_mean[TOK];
__device__ float g_rstd[TOK];
__device__ float g_slots[B_*S_*D_];
__device__ float g_q[B_*S_*D_];
__device__ float g_attn[TOK*S_];     // softmax + 1e-8, pre-renorm
__device__ float g_colsum[B_*S_];
__device__ float g_updates[B_*S_*D_];
__device__ uint32_t g_xh[TOK*128];   // x as bf16x2 hi pairs (64 MB)
__device__ uint32_t g_xl[TOK*128];   // x residual bf16x2 pairs
__device__ uint32_t g_wh[512*128];   // (g∘[wk;wv]) hi pairs
__device__ uint32_t g_wl[512*128];   // residual pairs
__device__ float g_sg[512];          // row sums of g∘W
__device__ float g_sb[512];          // W @ ln_in_b

__device__ __forceinline__ float sigmoidf_(float x) { return 1.f / (1.f + expf(-x)); }

// bf16 mma.sync m16n8k16 (baseline PTX, sm_80+)
__device__ __forceinline__ void mma_bf16(float* c, const uint32_t* a, const uint32_t* b) {
    asm volatile(
        "mma.sync.aligned.m16n8k16.row.col.f32.bf16.bf16.f32 "
        "{%0,%1,%2,%3}, {%4,%5,%6,%7}, {%8,%9}, {%0,%1,%2,%3};"
        : "+f"(c[0]), "+f"(c[1]), "+f"(c[2]), "+f"(c[3])
        : "r"(a[0]), "r"(a[1]), "r"(a[2]), "r"(a[3]), "r"(b[0]), "r"(b[1]));
}
__device__ __forceinline__ void pckpair(float x, float y, uint32_t& hi, uint32_t& lo) {
    __nv_bfloat162 h = __floats2bfloat162_rn(x, y);
    float xr = x - __bfloat162float(h.x);
    float yr = y - __bfloat162float(h.y);
    __nv_bfloat162 l = __floats2bfloat162_rn(xr, yr);
    hi = *reinterpret_cast<uint32_t*>(&h);
    lo = *reinterpret_cast<uint32_t*>(&l);
}
__device__ __forceinline__ uint32_t smem_u32(const void* p) {
    uint32_t a;
    asm("{ .reg .u64 t; cvta.to.shared.u64 t, %1; cvt.u32.u64 %0, t; }" : "=r"(a) : "l"(p));
    return a;
}
__device__ __forceinline__ void cp16(uint32_t dst, const void* src) {
    asm volatile("cp.async.cg.shared.global [%0], [%1], 16;" :: "r"(dst), "l"(src));
}
#define CP_COMMIT() asm volatile("cp.async.commit_group;" ::: "memory")
#define CP_WAIT(n)  asm volatile("cp.async.wait_group %0;" :: "n"(n) : "memory")

// ---------------- K0: prep packed W, sg, sb --------------------------------
__global__ void k_prep(const float* __restrict__ wk, const float* __restrict__ wv,
                       const float* __restrict__ lng, const float* __restrict__ lnb) {
    int j = blockIdx.x * 8 + (threadIdx.x >> 5);
    int lane = threadIdx.x & 31;
    const float* wr = (j < 256) ? (wk + (size_t)j*256) : (wv + (size_t)(j-256)*256);
    float4 wa = *(const float4*)&wr[lane*8];
    float4 wb = *(const float4*)&wr[lane*8+4];
    float4 ga = *(const float4*)&lng[lane*8];
    float4 gb = *(const float4*)&lng[lane*8+4];
    float4 ba = *(const float4*)&lnb[lane*8];
    float4 bb = *(const float4*)&lnb[lane*8+4];
    float w0 = wa.x*ga.x, w1 = wa.y*ga.y, w2 = wa.z*ga.z, w3 = wa.w*ga.w;
    float w4 = wb.x*gb.x, w5 = wb.y*gb.y, w6 = wb.z*gb.z, w7 = wb.w*gb.w;
    uint4 hi, lo;
    pckpair(w0, w1, hi.x, lo.x);
    pckpair(w2, w3, hi.y, lo.y);
    pckpair(w4, w5, hi.z, lo.z);
    pckpair(w6, w7, hi.w, lo.w);
    *(uint4*)&g_wh[(size_t)j*128 + lane*4] = hi;
    *(uint4*)&g_wl[(size_t)j*128 + lane*4] = lo;
    float ssg = w0+w1+w2+w3+w4+w5+w6+w7;
    float ssb = wa.x*ba.x+wa.y*ba.y+wa.z*ba.z+wa.w*ba.w
              + wb.x*bb.x+wb.y*bb.y+wb.z*bb.z+wb.w*bb.w;
    #pragma unroll
    for (int o = 16; o; o >>= 1) {
        ssg += __shfl_xor_sync(0xffffffffu, ssg, o);
        ssb += __shfl_xor_sync(0xffffffffu, ssb, o);
    }
    if (lane == 0) { g_sg[j] = ssg; g_sb[j] = ssb; }
}

// ---------------- K1: per-token mean/rstd + packed x ------------------------
__global__ void k_meanvar(const float* __restrict__ x) {
    int warp = threadIdx.x >> 5, lane = threadIdx.x & 31;
    int tok = blockIdx.x * 8 + warp;
    const float4* row = (const float4*)(x + (size_t)tok * D_);
    float4 a = row[lane*2], b = row[lane*2+1];
    uint4 hi, lo;
    pckpair(a.x, a.y, hi.x, lo.x);
    pckpair(a.z, a.w, hi.y, lo.y);
    pckpair(b.x, b.y, hi.z, lo.z);
    pckpair(b.z, b.w, hi.w, lo.w);
    *(uint4*)&g_xh[(size_t)tok*128 + lane*4] = hi;
    *(uint4*)&g_xl[(size_t)tok*128 + lane*4] = lo;
    float s = a.x+a.y+a.z+a.w + b.x+b.y+b.z+b.w;
    float q = a.x*a.x+a.y*a.y+a.z*a.z+a.w*a.w + b.x*b.x+b.y*b.y+b.z*b.z+b.w*b.w;
    #pragma unroll
    for (int o = 16; o; o >>= 1) {
        s += __shfl_xor_sync(0xffffffffu, s, o);
        q += __shfl_xor_sync(0xffffffffu, q, o);
    }
    if (lane == 0) {
        float m = s * (1.f/256.f);
        g_mean[tok] = m;
        g_rstd[tok] = rsqrtf(q * (1.f/256.f) - m*m + EPS);
    }
}

// ---------------- K2: split-bf16 K/V projection GEMM ------------------------
// grid = (4, 1024). cb: 0,1 -> k cols 0/128; 2,3 -> v cols 0/128.
// GEMM on raw x vs Wg (both split bf16 hi/lo, k-pair packed);
// LN applied in epilogue: out = r*acc - (m*r)*sg + sb + bias
#define PITP 20                       // uint32 pitch per row (16 data + 4 pad)
#define PLANE (128*PITP)              // 2560 uint32 per plane

__global__ void __launch_bounds__(256, 2) k_kv_bf(
    const float* __restrict__ bk, const float* __restrict__ bv)
{
    extern __shared__ uint32_t sm[];
    // buffer b at sm + b*4*PLANE: [Ah][Al][Bh][Bl]
    int tid = threadIdx.x;
    int wid = tid >> 5, lane = tid & 31;
    int m0 = blockIdx.y * 128;
    int cb = blockIdx.x;
    const float* bias = (cb < 2) ? bk : bv;
    float* outp       = (cb < 2) ? g_k : g_v;
    int colbase = (cb & 1) * 128;
    int jbase   = cb * 128;

    // loader geometry: per plane 512 chunks of 16B; thread does rows lr, lr+64
    int lr = tid >> 2;
    int lc = (tid & 3) * 4;           // uint32 col 0,4,8,12
    const uint32_t* xh0 = g_xh + (size_t)(m0 + lr) * 128 + lc;
    const uint32_t* xl0 = g_xl + (size_t)(m0 + lr) * 128 + lc;
    const uint32_t* wh0 = g_wh + (size_t)(jbase + lr) * 128 + lc;
    const uint32_t* wl0 = g_wl + (size_t)(jbase + lr) * 128 + lc;
    const int R64 = 64 * 128;         // row offset in gmem

    uint32_t sbase = smem_u32(sm);
    uint32_t d0 = sbase + (lr*PITP + lc) * 4;
    uint32_t d1 = sbase + ((lr+64)*PITP + lc) * 4;
    const uint32_t BUFB = 4*PLANE*4;  // bytes per buffer
    const uint32_t PLB = PLANE*4;

    float acc[2][8][4];
    #pragma unroll
    for (int mf = 0; mf < 2; mf++)
        #pragma unroll
        for (int nf = 0; nf < 8; nf++)
            #pragma unroll
            for (int j = 0; j < 4; j++) acc[mf][nf][j] = 0.f;

    int wm = (wid >> 1) * 32;
    int wn = (wid & 1) * 64;
    int g  = lane >> 2, q = lane & 3;

    // prologue: stage 0
    cp16(d0,         xh0); cp16(d1,         xh0 + R64);
    cp16(d0 + PLB,   xl0); cp16(d1 + PLB,   xl0 + R64);
    cp16(d0 + 2*PLB, wh0); cp16(d1 + 2*PLB, wh0 + R64);
    cp16(d0 + 3*PLB, wl0); cp16(d1 + 3*PLB, wl0 + R64);
    CP_COMMIT();

    for (int s = 0; s < 8; ++s) {
        int buf = s & 1;
        if (s < 7) {
            int nb = (s + 1) & 1;
            int kp = (s + 1) * 16;    // packed uint32 offset
            uint32_t db0 = d0 + nb*BUFB, db1 = d1 + nb*BUFB;
            cp16(db0,         xh0 + kp); cp16(db1,         xh0 + R64 + kp);
            cp16(db0 + PLB,   xl0 + kp); cp16(db1 + PLB,   xl0 + R64 + kp);
            cp16(db0 + 2*PLB, wh0 + kp); cp16(db1 + 2*PLB, wh0 + R64 + kp);
            cp16(db0 + 3*PLB, wl0 + kp); cp16(db1 + 3*PLB, wl0 + R64 + kp);
            CP_COMMIT();
            CP_WAIT(1);
        } else {
            CP_WAIT(0);
        }
        __syncthreads();

        const uint32_t* Ah = sm + buf*4*PLANE;
        const uint32_t* Al = Ah + PLANE;
        const uint32_t* Bh = Al + PLANE;
        const uint32_t* Bl = Bh + PLANE;

        #pragma unroll
        for (int k16 = 0; k16 < 2; k16++) {
            int kb = k16 * 8;
            uint32_t ah[2][4], al[2][4];
            #pragma unroll
            for (int mf = 0; mf < 2; mf++) {
                int r = (wm + mf*16 + g) * PITP + kb + q;
                ah[mf][0] = Ah[r];            ah[mf][1] = Ah[r + 8*PITP];
                ah[mf][2] = Ah[r + 4];        ah[mf][3] = Ah[r + 8*PITP + 4];
                al[mf][0] = Al[r];            al[mf][1] = Al[r + 8*PITP];
                al[mf][2] = Al[r + 4];        al[mf][3] = Al[r + 8*PITP + 4];
            }
            #pragma unroll
            for (int nf = 0; nf < 8; nf++) {
                int rb = (wn + nf*8 + g) * PITP + kb + q;
                uint32_t bh[2] = { Bh[rb], Bh[rb + 4] };
                uint32_t bl[2] = { Bl[rb], Bl[rb + 4] };
                #pragma unroll
                for (int mf = 0; mf < 2; mf++) {
                    mma_bf16(acc[mf][nf], ah[mf], bh);
                    mma_bf16(acc[mf][nf], ah[mf], bl);
                    mma_bf16(acc[mf][nf], al[mf], bh);
                }
            }
        }
        __syncthreads();
    }

    // ---- epilogue: LN affine + bias + store ----
    float rr[2][2], mr[2][2];
    #pragma unroll
    for (int mf = 0; mf < 2; mf++) {
        int r0 = m0 + wm + mf*16 + g;
        rr[mf][0] = g_rstd[r0];     mr[mf][0] = g_mean[r0]   * rr[mf][0];
        rr[mf][1] = g_rstd[r0+8];   mr[mf][1] = g_mean[r0+8] * rr[mf][1];
    }
    #pragma unroll
    for (int nf = 0; nf < 8; nf++) {
        int cl = wn + nf*8 + q*2;           // local col 0..127
        int j  = jbase + cl;
        float2 sg2 = make_float2(g_sg[j], g_sg[j+1]);
        float2 cc  = make_float2(g_sb[j]   + bias[colbase + cl],
                                 g_sb[j+1] + bias[colbase + cl + 1]);
        #pragma unroll
        for (int mf = 0; mf < 2; mf++) {
            int r0 = m0 + wm + mf*16 + g;
            float2 o0, o1;
            o0.x = rr[mf][0]*acc[mf][nf][0] - mr[mf][0]*sg2.x + cc.x;
            o0.y = rr[mf][0]*acc[mf][nf][1] - mr[mf][0]*sg2.y + cc.y;
            o1.x = rr[mf][1]*acc[mf][nf][2] - mr[mf][1]*sg2.x + cc.x;
            o1.y = rr[mf][1]*acc[mf][nf][3] - mr[mf][1]*sg2.y + cc.y;
            *(float2*)&outp[(size_t)r0 * 256 + colbase + cl]       = o0;
            *(float2*)&outp[(size_t)(r0+8) * 256 + colbase + cl]   = o1;
        }
    }
}

// ---------------- K3: slots init -------------------------------------------
__global__ void k_init_slots(const float* __restrict__ noise,
                             const float* __restrict__ mu,
                             const float* __restrict__ sigma_raw) {
    int i = blockIdx.x*blockDim.x + threadIdx.x;
    if (i < B_*S_*D_) {
        int d = i & 255;
        float sr = sigma_raw[d];
        float sp = (sr > 20.f) ? sr : log1pf(expf(sr));
        g_slots[i] = mu[d] + sp * noise[i];
    }
}

// ---------------- K4: q = LN(slots) @ wq^T + bq, block per batch ------------
__global__ void __launch_bounds__(256) k_qproj2(
    const float* __restrict__ g, const float* __restrict__ bln,
    const float* __restrict__ wq, const float* __restrict__ bq)
{
    __shared__ __align__(16) float ssl[8][256];
    __shared__ __align__(16) float sa[8][256];
    __shared__ float sm[8], sr[8];
    int b = blockIdx.x, t = threadIdx.x;
    #pragma unroll
    for (int s = 0; s < 8; s++) {
        ssl[s][t] = g_slots[(b*8+s)*256 + t];
        g_updates[(b*8+s)*256 + t] = 0.f;
    }
    if (t < 8) g_colsum[b*8 + t] = 0.f;
    __syncthreads();
    int w = t >> 5, lane = t & 31;
    {
        float s1 = 0.f, s2 = 0.f;
        #pragma unroll
        for (int e = 0; e < 8; e++) {
            float v = ssl[w][lane + e*32];
            s1 += v; s2 += v*v;
        }
        #pragma unroll
        for (int o = 16; o; o >>= 1) {
            s1 += __shfl_xor_sync(0xffffffffu, s1, o);
            s2 += __shfl_xor_sync(0xffffffffu, s2, o);
        }
        if (lane == 0) {
            float m = s1 * (1.f/256.f);
            sm[w] = m;
            sr[w] = rsqrtf(s2 * (1.f/256.f) - m*m + EPS);
        }
    }
    __syncthreads();
    float gt = g[t], bt = bln[t];
    #pragma unroll
    for (int s = 0; s < 8; s++)
        sa[s][t] = (ssl[s][t] - sm[s]) * sr[s] * gt + bt;
    __syncthreads();

    float acc[8] = {0,0,0,0,0,0,0,0};
    const float* wr = wq + (size_t)t * 256;
    #pragma unroll 2
    for (int e = 0; e < 256; e += 4) {
        float4 w4 = *(const float4*)&wr[e];
        #pragma unroll
        for (int s = 0; s < 8; s++) {
            float4 a4 = *(const float4*)&sa[s][e];
            acc[s] += w4.x*a4.x + w4.y*a4.y + w4.z*a4.z + w4.w*a4.w;
        }
    }
    float bqt = bq[t];
    #pragma unroll
    for (int s = 0; s < 8; s++)
        g_q[(b*8+s)*256 + t] = acc[s] + bqt;
}

// ---------------- K5: logits + softmax(+1e-8) + column sums -----------------
__global__ void __launch_bounds__(256) k_logits() {
    int b = blockIdx.y, chunk = blockIdx.x;           // chunk 0..15
    int warp = threadIdx.x >> 5, lane = threadIdx.x & 31;

    float qr[8][8];
    const float* qb = g_q + b*S_*D_;
    #pragma unroll
    for (int s = 0; s < 8; s++) {
        float4 a = *(const float4*)&qb[s*256 + lane*8];
        float4 c = *(const float4*)&qb[s*256 + lane*8 + 4];
        qr[s][0]=a.x; qr[s][1]=a.y; qr[s][2]=a.z; qr[s][3]=a.w;
        qr[s][4]=c.x; qr[s][5]=c.y; qr[s][6]=c.z; qr[s][7]=c.w;
    }

    float csum[8] = {0,0,0,0,0,0,0,0};
    for (int t = warp; t < 256; t += 8) {
        int n = chunk*256 + t;
        const float* krow = g_k + ((size_t)(b*N_ + n))*D_ + lane*8;
        float4 a = *(const float4*)krow;
        float4 c = *(const float4*)(krow + 4);
        float kf[8] = {a.x,a.y,a.z,a.w,c.x,c.y,c.z,c.w};

        float lg[8];
        #pragma unroll
        for (int s = 0; s < 8; s++) {
            float p = 0.f;
            #pragma unroll
            for (int j = 0; j < 8; j++) p += kf[j]*qr[s][j];
            #pragma unroll
            for (int o = 16; o; o >>= 1) p += __shfl_xor_sync(0xffffffffu, p, o);
            lg[s] = p * 0.0625f;   // * SLOT_DIM^-0.5
        }
        float mx = lg[0];
        #pragma unroll
        for (int s = 1; s < 8; s++) mx = fmaxf(mx, lg[s]);
        float e[8], sum = 0.f;
        #pragma unroll
        for (int s = 0; s < 8; s++) { e[s] = expf(lg[s]-mx); sum += e[s]; }
        float inv = 1.f/sum;
        float p8[8];
        #pragma unroll
        for (int s = 0; s < 8; s++) p8[s] = e[s]*inv + 1e-8f;

        if (lane == 0) {
            float* dst = g_attn + ((size_t)(b*N_ + n))*8;
            ((float4*)dst)[0] = make_float4(p8[0],p8[1],p8[2],p8[3]);
            ((float4*)dst)[1] = make_float4(p8[4],p8[5],p8[6],p8[7]);
            #pragma unroll
            for (int s = 0; s < 8; s++) csum[s] += p8[s];
        }
    }
    if (lane == 0) {
        #pragma unroll
        for (int s = 0; s < 8; s++) atomicAdd(&g_colsum[b*8 + s], csum[s]);
    }
}

// ---------------- K6: updates[b,s,d] = sum_n attn_raw * v ------------------
__global__ void __launch_bounds__(256) k_updates() {
    int b = blockIdx.y, chunk = blockIdx.x;   // 4 chunks of 1024 tokens
    int d = threadIdx.x;
    float acc[8] = {0,0,0,0,0,0,0,0};
    __shared__ float sA[32][8];
    int tok0 = b*N_ + chunk*1024;
    for (int base = 0; base < 1024; base += 32) {
        int li = threadIdx.x;
        sA[li >> 3][li & 7] = g_attn[(size_t)(tok0 + base + (li >> 3))*8 + (li & 7)];
        __syncthreads();
        #pragma unroll 4
        for (int i = 0; i < 32; i++) {
            float vv = g_v[(size_t)(tok0 + base + i)*D_ + d];
            #pragma unroll
            for (int s = 0; s < 8; s++) acc[s] += sA[i][s]*vv;
        }
        __syncthreads();
    }
    #pragma unroll
    for (int s = 0; s < 8; s++)
        atomicAdd(&g_updates[(b*8 + s)*D_ + d], acc[s]);
}

// ---------------- K7: GRU + LN + MLP, block per (batch, slot-pair) ---------
__global__ void __launch_bounds__(256) k_gru2(
    const float* __restrict__ w_ih, const float* __restrict__ w_hh,
    const float* __restrict__ b_ih, const float* __restrict__ b_hh,
    const float* __restrict__ lng,  const float* __restrict__ lnb,
    const float* __restrict__ w1,   const float* __restrict__ b1,
    const float* __restrict__ w2,   const float* __restrict__ b2,
    float* __restrict__ out_slots)
{
    __shared__ __align__(16) float su[2][256];
    __shared__ __align__(16) float sh[2][256];
    __shared__ __align__(16) float sa[2][256];
    __shared__ __align__(16) float sh1[2][512];
    __shared__ float sm[2], sr2[2];

    int b = blockIdx.x >> 2;
    int p = blockIdx.x & 3;
    int row0 = b*8 + p*2;
    int t = threadIdx.x;

    #pragma unroll
    for (int sl = 0; sl < 2; sl++) {
        float ics = 1.f / g_colsum[row0 + sl];
        su[sl][t] = g_updates[(row0+sl)*256 + t] * ics;
        sh[sl][t] = g_slots[(row0+sl)*256 + t];
    }
    __syncthreads();

    float xr[2], xz[2], xn[2], hr[2], hz[2], hn[2];
    #pragma unroll
    for (int sl = 0; sl < 2; sl++) {
        xr[sl] = b_ih[t]; xz[sl] = b_ih[256+t]; xn[sl] = b_ih[512+t];
        hr[sl] = b_hh[t]; hz[sl] = b_hh[256+t]; hn[sl] = b_hh[512+t];
    }
    const float* wir = w_ih + (size_t)t*256;
    const float* wiz = w_ih + (size_t)(256+t)*256;
    const float* win = w_ih + (size_t)(512+t)*256;
    const float* whr = w_hh + (size_t)t*256;
    const float* whz = w_hh + (size_t)(256+t)*256;
    const float* whn = w_hh + (size_t)(512+t)*256;

    #pragma unroll 2
    for (int e = 0; e < 256; e += 4) {
        float4 wr4 = *(const float4*)&wir[e];
        float4 wz4 = *(const float4*)&wiz[e];
        float4 wn4 = *(const float4*)&win[e];
        float4 vr4 = *(const float4*)&whr[e];
        float4 vz4 = *(const float4*)&whz[e];
        float4 vn4 = *(const float4*)&whn[e];
        #pragma unroll
        for (int sl = 0; sl < 2; sl++) {
            float4 u4 = *(const float4*)&su[sl][e];
            float4 h4 = *(const float4*)&sh[sl][e];
            xr[sl] += wr4.x*u4.x + wr4.y*u4.y + wr4.z*u4.z + wr4.w*u4.w;
            xz[sl] += wz4.x*u4.x + wz4.y*u4.y + wz4.z*u4.z + wz4.w*u4.w;
            xn[sl] += wn4.x*u4.x + wn4.y*u4.y + wn4.z*u4.z + wn4.w*u4.w;
            hr[sl] += vr4.x*h4.x + vr4.y*h4.y + vr4.z*h4.z + vr4.w*h4.w;
            hz[sl] += vz4.x*h4.x + vz4.y*h4.y + vz4.z*h4.z + vz4.w*h4.w;
            hn[sl] += vn4.x*h4.x + vn4.y*h4.y + vn4.z*h4.z + vn4.w*h4.w;
        }
    }
    float hnew[2];
    #pragma unroll
    for (int sl = 0; sl < 2; sl++) {
        float r = sigmoidf_(xr[sl] + hr[sl]);
        float z = sigmoidf_(xz[sl] + hz[sl]);
        float nn = tanhf(xn[sl] + r*hn[sl]);
        hnew[sl] = (1.f - z)*nn + z*sh[sl][t];
    }
    __syncthreads();
    su[0][t] = hnew[0]; su[1][t] = hnew[1];
    __syncthreads();
    int w = t >> 5, lane = t & 31;
    if (w < 2) {
        float s1 = 0.f, s2 = 0.f;
        #pragma unroll
        for (int e = 0; e < 8; e++) {
            float v = su[w][lane + e*32];
            s1 += v; s2 += v*v;
        }
        #pragma unroll
        for (int o = 16; o; o >>= 1) {
            s1 += __shfl_xor_sync(0xffffffffu, s1, o);
            s2 += __shfl_xor_sync(0xffffffffu, s2, o);
        }
        if (lane == 0) {
            float m = s1 * (1.f/256.f);
            sm[w] = m;
            sr2[w] = rsqrtf(s2 * (1.f/256.f) - m*m + EPS);
        }
    }
    __syncthreads();
    float gt = lng[t], bt = lnb[t];
    sa[0][t] = (hnew[0] - sm[0]) * sr2[0] * gt + bt;
    sa[1][t] = (hnew[1] - sm[1]) * sr2[1] * gt + bt;
    __syncthreads();

    float a1[2] = {b1[t], b1[t]};
    float a2[2] = {b1[256+t], b1[256+t]};
    const float* w1a = w1 + (size_t)t*256;
    const float* w1b = w1 + (size_t)(256+t)*256;
    #pragma unroll 2
    for (int e = 0; e < 256; e += 4) {
        float4 wa = *(const float4*)&w1a[e];
        float4 wb = *(const float4*)&w1b[e];
        #pragma unroll
        for (int sl = 0; sl < 2; sl++) {
            float4 s4 = *(const float4*)&sa[sl][e];
            a1[sl] += wa.x*s4.x + wa.y*s4.y + wa.z*s4.z + wa.w*s4.w;
            a2[sl] += wb.x*s4.x + wb.y*s4.y + wb.z*s4.z + wb.w*s4.w;
        }
    }
    sh1[0][t] = fmaxf(a1[0], 0.f); sh1[0][256+t] = fmaxf(a2[0], 0.f);
    sh1[1][t] = fmaxf(a1[1], 0.f); sh1[1][256+t] = fmaxf(a2[1], 0.f);
    __syncthreads();

    float o[2] = {b2[t], b2[t]};
    const float* w2r = w2 + (size_t)t*512;
    #pragma unroll 2
    for (int e = 0; e < 512; e += 4) {
        float4 w4 = *(const float4*)&w2r[e];
        #pragma unroll
        for (int sl = 0; sl < 2; sl++) {
            float4 h4 = *(const float4*)&sh1[sl][e];
            o[sl] += w4.x*h4.x + w4.y*h4.y + w4.z*h4.z + w4.w*h4.w;
        }
    }
    #pragma unroll
    for (int sl = 0; sl < 2; sl++) {
        float res = hnew[sl] + o[sl];
        g_slots[(row0+sl)*256 + t] = res;
        if (out_slots) out_slots[(row0+sl)*256 + t] = res;
    }
}

// ---------------- K8: final attn normalize to d_out -------------------------
__global__ void k_attn_out(float* __restrict__ dst) {
    int i = blockIdx.x*blockDim.x + threadIdx.x;
    if (i < TOK*S_) {
        int s = i & 7;
        int b = i >> 15;
        dst[i] = g_attn[i] / g_colsum[b*8 + s];
    }
}

// ---------------- host ------------------------------------------------------
extern "C" void kernel_launch(void* const* d_in, const int* in_sizes, int n_in,
                              void* d_out, int out_size) {
    const float* inputs     = (const float*)d_in[0];
    const float* init_noise = (const float*)d_in[1];
    const float* mu         = (const float*)d_in[2];
    const float* sigma_raw  = (const float*)d_in[3];
    const float* ln_in_g    = (const float*)d_in[4];
    const float* ln_in_b    = (const float*)d_in[5];
    const float* ln_s_g     = (const float*)d_in[6];
    const float* ln_s_b     = (const float*)d_in[7];
    const float* ln_m_g     = (const float*)d_in[8];
    const float* ln_m_b     = (const float*)d_in[9];
    const float* wq         = (const float*)d_in[10];
    const float* bq         = (const float*)d_in[11];
    const float* wk         = (const float*)d_in[12];
    const float* bk         = (const float*)d_in[13];
    const float* wv         = (const float*)d_in[14];
    const float* bv         = (const float*)d_in[15];
    const float* w_ih       = (const float*)d_in[16];
    const float* w_hh       = (const float*)d_in[17];
    const float* b_ih       = (const float*)d_in[18];
    const float* b_hh       = (const float*)d_in[19];
    const float* w1         = (const float*)d_in[20];
    const float* b1         = (const float*)d_in[21];
    const float* w2         = (const float*)d_in[22];
    const float* b2         = (const float*)d_in[23];
    float* out = (float*)d_out;

    const int GEMM_SMEM = 2 * 4 * PLANE * 4;   // 80 KB
    static int smem_set = 0;
    if (!smem_set) {
        cudaFuncSetAttribute(k_kv_bf, cudaFuncAttributeMaxDynamicSharedMemorySize, GEMM_SMEM);
        smem_set = 1;
    }

    k_prep<<<64, 256>>>(wk, wv, ln_in_g, ln_in_b);
    k_meanvar<<<TOK/8, 256>>>(inputs);
    k_kv_bf<<<dim3(4, TOK/128), 256, GEMM_SMEM>>>(bk, bv);
    k_init_slots<<<(B_*S_*D_ + 255)/256, 256>>>(init_noise, mu, sigma_raw);

    for (int it = 0; it < 3; ++it) {
        bool last = (it == 2);
        k_qproj2<<<B_, 256>>>(ln_s_g, ln_s_b, wq, bq);
        k_logits<<<dim3(16, B_), 256>>>();
        k_updates<<<dim3(4, B_), 256>>>();
        k_gru2<<<B_*4, 256>>>(w_ih, w_hh, b_ih, b_hh, ln_m_g, ln_m_b,
                              w1, b1, w2, b2, last ? out : nullptr);
        if (last) k_attn_out<<<(TOK*S_ + 255)/256, 256>>>(out + B_*S_*D_);
    }
}

// round 6
// speedup vs baseline: 2.6794x; 1.5436x over previous
#include <cuda_runtime.h>
#include <cstdint>
#include <math.h>

#define B_   32
#define N_   4096
#define D_   256
#define S_   8
#define H_   512
#define TOK  (B_*N_)      // 131072
#define EPS  1e-5f
#define SCALE 0.0625f     // 256^-0.5

// ---------------- scratch (device globals; no runtime allocation) ----------
__device__ float g_mean[TOK];
__device__ float g_rstd[TOK];
__device__ float g_slots[B_*S_*D_];
__device__ float g_p[B_*S_*D_];      // pg = scale * g ∘ (q @ wk)
__device__ float g_S1[B_*S_];
__device__ float g_S2[B_*S_];
__device__ float g_attn[TOK*S_];     // softmax + 1e-8, pre-renorm
__device__ float g_cs[B_*S_];        // colsum
__device__ float g_t1[B_*S_];        // sum a*r*m
__device__ float g_U[B_*S_*D_];      // sum_n a*r*x[n]
__device__ float g_wkgT[D_*D_];      // wkgT[d][j] = ln_in_g[d]*wk[j][d]
__device__ float g_wkb[D_];          // wk @ ln_in_b + bk

__device__ __forceinline__ float sigmoidf_(float x) { return 1.f / (1.f + expf(-x)); }

// ---------------- prep: transposed g-scaled wk -------------------------------
__global__ void k_prep_t(const float* __restrict__ wk, const float* __restrict__ lng) {
    __shared__ float tile[32][33];
    int j0 = blockIdx.y * 32, d0 = blockIdx.x * 32;
    int tx = threadIdx.x, ty = threadIdx.y;   // (32,8)
    #pragma unroll
    for (int r = 0; r < 4; r++)
        tile[ty + 8*r][tx] = wk[(size_t)(j0 + ty + 8*r) * 256 + d0 + tx];
    __syncthreads();
    #pragma unroll
    for (int r = 0; r < 4; r++) {
        int d = d0 + ty + 8*r;
        g_wkgT[(size_t)d * 256 + j0 + tx] = lng[d] * tile[tx][ty + 8*r];
    }
}

// ---------------- prep: wkb[j] = wk[j,:]·ln_in_b + bk[j] --------------------
__global__ void k_prep_b(const float* __restrict__ wk, const float* __restrict__ lnb,
                         const float* __restrict__ bk) {
    int j = threadIdx.x;
    const float* wr = wk + (size_t)j * 256;
    float acc = bk[j];
    #pragma unroll 4
    for (int e = 0; e < 256; e += 4) {
        float4 w4 = *(const float4*)&wr[e];
        float4 b4 = *(const float4*)&lnb[e];
        acc += w4.x*b4.x + w4.y*b4.y + w4.z*b4.z + w4.w*b4.w;
    }
    g_wkb[j] = acc;
}

// ---------------- K1: per-token mean/rstd of inputs ------------------------
__global__ void k_meanvar(const float* __restrict__ x) {
    int warp = threadIdx.x >> 5, lane = threadIdx.x & 31;
    int tok = blockIdx.x * 8 + warp;
    const float4* row = (const float4*)(x + (size_t)tok * D_);
    float4 a = row[lane*2], b = row[lane*2+1];
    float s = a.x+a.y+a.z+a.w + b.x+b.y+b.z+b.w;
    float q = a.x*a.x+a.y*a.y+a.z*a.z+a.w*a.w + b.x*b.x+b.y*b.y+b.z*b.z+b.w*b.w;
    #pragma unroll
    for (int o = 16; o; o >>= 1) {
        s += __shfl_xor_sync(0xffffffffu, s, o);
        q += __shfl_xor_sync(0xffffffffu, q, o);
    }
    if (lane == 0) {
        float m = s * (1.f/256.f);
        g_mean[tok] = m;
        g_rstd[tok] = rsqrtf(q * (1.f/256.f) - m*m + EPS);
    }
}

// ---------------- K3: slots init -------------------------------------------
__global__ void k_init_slots(const float* __restrict__ noise,
                             const float* __restrict__ mu,
                             const float* __restrict__ sigma_raw) {
    int i = blockIdx.x*blockDim.x + threadIdx.x;
    if (i < B_*S_*D_) {
        int d = i & 255;
        float sr = sigma_raw[d];
        float sp = (sr > 20.f) ? sr : log1pf(expf(sr));
        g_slots[i] = mu[d] + sp * noise[i];
    }
}

// ---------------- K4: per-batch q proj + pg/S1/S2 + zeroing -----------------
__global__ void __launch_bounds__(256) k_qproj3(
    const float* __restrict__ g, const float* __restrict__ bln,
    const float* __restrict__ wq, const float* __restrict__ bq)
{
    __shared__ __align__(16) float sa[8][256];
    __shared__ __align__(16) float sq[8][256];
    __shared__ float sm[8], sr[8];
    __shared__ float red1[8][8], red2[8][8];
    int b = blockIdx.x, t = threadIdx.x;
    int w = t >> 5, lane = t & 31;

    // zero accumulators for this batch
    #pragma unroll
    for (int s = 0; s < 8; s++) {
        g_U[(b*8+s)*256 + t] = 0.f;
        sa[s][t] = g_slots[(b*8+s)*256 + t];
    }
    if (t < 8) { g_cs[b*8 + t] = 0.f; g_t1[b*8 + t] = 0.f; }
    __syncthreads();

    // stats: warp w handles slot w
    {
        float s1 = 0.f, s2 = 0.f;
        #pragma unroll
        for (int e = 0; e < 8; e++) {
            float v = sa[w][lane + e*32];
            s1 += v; s2 += v*v;
        }
        #pragma unroll
        for (int o = 16; o; o >>= 1) {
            s1 += __shfl_xor_sync(0xffffffffu, s1, o);
            s2 += __shfl_xor_sync(0xffffffffu, s2, o);
        }
        if (lane == 0) {
            float m = s1 * (1.f/256.f);
            sm[w] = m;
            sr[w] = rsqrtf(s2 * (1.f/256.f) - m*m + EPS);
        }
    }
    __syncthreads();
    float gt = g[t], bt = bln[t];
    #pragma unroll
    for (int s = 0; s < 8; s++)
        sa[s][t] = (sa[s][t] - sm[s]) * sr[s] * gt + bt;
    __syncthreads();

    // q[s][t] = sa[s]·wq[t,:] + bq[t]
    {
        float acc[8] = {0,0,0,0,0,0,0,0};
        const float* wr = wq + (size_t)t * 256;
        #pragma unroll 2
        for (int e = 0; e < 256; e += 4) {
            float4 w4 = *(const float4*)&wr[e];
            #pragma unroll
            for (int s = 0; s < 8; s++) {
                float4 a4 = *(const float4*)&sa[s][e];
                acc[s] += w4.x*a4.x + w4.y*a4.y + w4.z*a4.z + w4.w*a4.w;
            }
        }
        float bqt = bq[t];
        #pragma unroll
        for (int s = 0; s < 8; s++) sq[s][t] = acc[s] + bqt;
    }
    __syncthreads();

    // pg[s][t] = SCALE * q[s]·wkgT[t,:]; S1 = sum_t pg; S2 = SCALE * q·wkb
    float pgv[8] = {0,0,0,0,0,0,0,0};
    {
        const float* wr = g_wkgT + (size_t)t * 256;
        #pragma unroll 2
        for (int e = 0; e < 256; e += 4) {
            float4 w4 = *(const float4*)&wr[e];
            #pragma unroll
            for (int s = 0; s < 8; s++) {
                float4 q4 = *(const float4*)&sq[s][e];
                pgv[s] += w4.x*q4.x + w4.y*q4.y + w4.z*q4.z + w4.w*q4.w;
            }
        }
    }
    float wkbt = g_wkb[t];
    float p2[8];
    #pragma unroll
    for (int s = 0; s < 8; s++) {
        pgv[s] *= SCALE;
        g_p[(b*8+s)*256 + t] = pgv[s];
        p2[s] = sq[s][t] * wkbt;
    }
    // block reductions of pgv (S1) and p2 (S2*scale^-1)
    #pragma unroll
    for (int s = 0; s < 8; s++) {
        float v1 = pgv[s], v2 = p2[s];
        #pragma unroll
        for (int o = 16; o; o >>= 1) {
            v1 += __shfl_xor_sync(0xffffffffu, v1, o);
            v2 += __shfl_xor_sync(0xffffffffu, v2, o);
        }
        if (lane == 0) { red1[s][w] = v1; red2[s][w] = v2; }
    }
    __syncthreads();
    if (t < 8) {
        float a1 = 0.f, a2 = 0.f;
        #pragma unroll
        for (int i = 0; i < 8; i++) { a1 += red1[t][i]; a2 += red2[t][i]; }
        g_S1[b*8 + t] = a1;
        g_S2[b*8 + t] = a2 * SCALE;
    }
}

// ---------------- K5: fused logits+softmax+U accumulation ------------------
// grid (16 chunks, 32 batches), 256 threads.
__global__ void __launch_bounds__(256) k_attn_fused(const float* __restrict__ x) {
    __shared__ __align__(16) float sA[32][8];   // a*r per token,slot
    __shared__ float scs[8][8], st1[8][8];
    int b = blockIdx.y, chunk = blockIdx.x;
    int t = threadIdx.x;
    int wid = t >> 5, lane = t & 31;

    // per-lane pg fragments + scalars
    float pg[8][8], S1[8], S2[8];
    {
        const float* pb = g_p + b*S_*D_;
        #pragma unroll
        for (int s = 0; s < 8; s++) {
            float4 a = *(const float4*)&pb[s*256 + lane*8];
            float4 c = *(const float4*)&pb[s*256 + lane*8 + 4];
            pg[s][0]=a.x; pg[s][1]=a.y; pg[s][2]=a.z; pg[s][3]=a.w;
            pg[s][4]=c.x; pg[s][5]=c.y; pg[s][6]=c.z; pg[s][7]=c.w;
            S1[s] = g_S1[b*8+s];
            S2[s] = g_S2[b*8+s];
        }
    }

    float u[8]  = {0,0,0,0,0,0,0,0};
    float csA[8] = {0,0,0,0,0,0,0,0};
    float t1A[8] = {0,0,0,0,0,0,0,0};
    int base_tok = b*N_ + chunk*256;

    for (int sub = 0; sub < 8; sub++) {
        int sub0 = sub * 32;
        // ---- pass 1: warp computes attn for its 4 tokens ----
        #pragma unroll
        for (int i = 0; i < 4; i++) {
            int loc = sub0 + wid*4 + i;
            int n = base_tok + loc;
            const float* xr = x + (size_t)n*256 + lane*8;
            float4 xa = *(const float4*)xr;
            float4 xb = *(const float4*)(xr + 4);
            float dt[8];
            #pragma unroll
            for (int s = 0; s < 8; s++) {
                dt[s] = xa.x*pg[s][0] + xa.y*pg[s][1] + xa.z*pg[s][2] + xa.w*pg[s][3]
                      + xb.x*pg[s][4] + xb.y*pg[s][5] + xb.z*pg[s][6] + xb.w*pg[s][7];
            }
            #pragma unroll
            for (int o = 16; o; o >>= 1) {
                #pragma unroll
                for (int s = 0; s < 8; s++)
                    dt[s] += __shfl_xor_sync(0xffffffffu, dt[s], o);
            }
            float r = g_rstd[n], m = g_mean[n];
            float rm = r * m;
            float lg[8];
            #pragma unroll
            for (int s = 0; s < 8; s++) lg[s] = r*dt[s] - rm*S1[s] + S2[s];
            float mx = lg[0];
            #pragma unroll
            for (int s = 1; s < 8; s++) mx = fmaxf(mx, lg[s]);
            float e[8], sum = 0.f;
            #pragma unroll
            for (int s = 0; s < 8; s++) { e[s] = expf(lg[s]-mx); sum += e[s]; }
            float inv = 1.f/sum;
            float a8[8], ar8[8];
            #pragma unroll
            for (int s = 0; s < 8; s++) {
                a8[s] = e[s]*inv + 1e-8f;
                ar8[s] = a8[s]*r;
                csA[s] += a8[s];
                t1A[s] += a8[s]*rm;
            }
            if (lane == 0) {
                float* dst = g_attn + (size_t)n*8;
                ((float4*)dst)[0] = make_float4(a8[0],a8[1],a8[2],a8[3]);
                ((float4*)dst)[1] = make_float4(a8[4],a8[5],a8[6],a8[7]);
                *(float4*)&sA[loc - sub0][0] = make_float4(ar8[0],ar8[1],ar8[2],ar8[3]);
                *(float4*)&sA[loc - sub0][4] = make_float4(ar8[4],ar8[5],ar8[6],ar8[7]);
            }
        }
        __syncthreads();
        // ---- pass 2: thread t accumulates U over 32 tokens (x rows in L1) ----
        const float* xcol = x + (size_t)(base_tok + sub0)*256 + t;
        #pragma unroll 4
        for (int i = 0; i < 32; i++) {
            float xv = xcol[(size_t)i*256];
            float4 p0 = *(const float4*)&sA[i][0];
            float4 p1 = *(const float4*)&sA[i][4];
            u[0] += p0.x*xv; u[1] += p0.y*xv; u[2] += p0.z*xv; u[3] += p0.w*xv;
            u[4] += p1.x*xv; u[5] += p1.y*xv; u[6] += p1.z*xv; u[7] += p1.w*xv;
        }
        __syncthreads();
    }

    // flush U
    #pragma unroll
    for (int s = 0; s < 8; s++)
        atomicAdd(&g_U[(b*8+s)*256 + t], u[s]);
    // flush cs/t1 (lane 0 of each warp holds warp-identical values)
    if (lane == 0) {
        #pragma unroll
        for (int s = 0; s < 8; s++) { scs[wid][s] = csA[s]; st1[wid][s] = t1A[s]; }
    }
    __syncthreads();
    if (t < 8) {
        float a = 0.f;
        #pragma unroll
        for (int i = 0; i < 8; i++) a += scs[i][t];
        atomicAdd(&g_cs[b*8 + t], a);
    } else if (t < 16) {
        int s = t - 8;
        float a = 0.f;
        #pragma unroll
        for (int i = 0; i < 8; i++) a += st1[i][s];
        atomicAdd(&g_t1[b*8 + s], a);
    }
}

// ---------------- K7: updates-from-U + GRU + LN + MLP ----------------------
__global__ void __launch_bounds__(256) k_gru3(
    const float* __restrict__ lng_in, const float* __restrict__ lnb_in,
    const float* __restrict__ wv,   const float* __restrict__ bv,
    const float* __restrict__ w_ih, const float* __restrict__ w_hh,
    const float* __restrict__ b_ih, const float* __restrict__ b_hh,
    const float* __restrict__ lng,  const float* __restrict__ lnb,
    const float* __restrict__ w1,   const float* __restrict__ b1,
    const float* __restrict__ w2,   const float* __restrict__ b2,
    float* __restrict__ out_slots)
{
    __shared__ __align__(16) float szn[2][256];
    __shared__ __align__(16) float su[2][256];
    __shared__ __align__(16) float sh[2][256];
    __shared__ __align__(16) float sa[2][256];
    __shared__ __align__(16) float sh1[2][512];
    __shared__ float sm[2], sr2[2];

    int b = blockIdx.x >> 2;
    int p = blockIdx.x & 3;
    int row0 = b*8 + p*2;
    int t = threadIdx.x;

    // zn = (g_in ∘ (U - t1))/cs + b_in
    #pragma unroll
    for (int sl = 0; sl < 2; sl++) {
        int row = row0 + sl;
        float csv = g_cs[row], t1v = g_t1[row];
        float Ut = g_U[row*256 + t];
        szn[sl][t] = lng_in[t] * (Ut - t1v) / csv + lnb_in[t];
        sh[sl][t] = g_slots[row*256 + t];
    }
    __syncthreads();

    // su = zn @ wv^T + bv
    {
        float a0 = 0.f, a1 = 0.f;
        const float* wr = wv + (size_t)t * 256;
        #pragma unroll 2
        for (int e = 0; e < 256; e += 4) {
            float4 w4 = *(const float4*)&wr[e];
            float4 z0 = *(const float4*)&szn[0][e];
            float4 z1 = *(const float4*)&szn[1][e];
            a0 += w4.x*z0.x + w4.y*z0.y + w4.z*z0.z + w4.w*z0.w;
            a1 += w4.x*z1.x + w4.y*z1.y + w4.z*z1.z + w4.w*z1.w;
        }
        float bvt = bv[t];
        su[0][t] = a0 + bvt;
        su[1][t] = a1 + bvt;
    }
    __syncthreads();

    float xr[2], xz[2], xn[2], hr[2], hz[2], hn[2];
    #pragma unroll
    for (int sl = 0; sl < 2; sl++) {
        xr[sl] = b_ih[t]; xz[sl] = b_ih[256+t]; xn[sl] = b_ih[512+t];
        hr[sl] = b_hh[t]; hz[sl] = b_hh[256+t]; hn[sl] = b_hh[512+t];
    }
    const float* wir = w_ih + (size_t)t*256;
    const float* wiz = w_ih + (size_t)(256+t)*256;
    const float* win = w_ih + (size_t)(512+t)*256;
    const float* whr = w_hh + (size_t)t*256;
    const float* whz = w_hh + (size_t)(256+t)*256;
    const float* whn = w_hh + (size_t)(512+t)*256;

    #pragma unroll 2
    for (int e = 0; e < 256; e += 4) {
        float4 wr4 = *(const float4*)&wir[e];
        float4 wz4 = *(const float4*)&wiz[e];
        float4 wn4 = *(const float4*)&win[e];
        float4 vr4 = *(const float4*)&whr[e];
        float4 vz4 = *(const float4*)&whz[e];
        float4 vn4 = *(const float4*)&whn[e];
        #pragma unroll
        for (int sl = 0; sl < 2; sl++) {
            float4 u4 = *(const float4*)&su[sl][e];
            float4 h4 = *(const float4*)&sh[sl][e];
            xr[sl] += wr4.x*u4.x + wr4.y*u4.y + wr4.z*u4.z + wr4.w*u4.w;
            xz[sl] += wz4.x*u4.x + wz4.y*u4.y + wz4.z*u4.z + wz4.w*u4.w;
            xn[sl] += wn4.x*u4.x + wn4.y*u4.y + wn4.z*u4.z + wn4.w*u4.w;
            hr[sl] += vr4.x*h4.x + vr4.y*h4.y + vr4.z*h4.z + vr4.w*h4.w;
            hz[sl] += vz4.x*h4.x + vz4.y*h4.y + vz4.z*h4.z + vz4.w*h4.w;
            hn[sl] += vn4.x*h4.x + vn4.y*h4.y + vn4.z*h4.z + vn4.w*h4.w;
        }
    }
    float hnew[2];
    #pragma unroll
    for (int sl = 0; sl < 2; sl++) {
        float r = sigmoidf_(xr[sl] + hr[sl]);
        float z = sigmoidf_(xz[sl] + hz[sl]);
        float nn = tanhf(xn[sl] + r*hn[sl]);
        hnew[sl] = (1.f - z)*nn + z*sh[sl][t];
    }
    __syncthreads();
    su[0][t] = hnew[0]; su[1][t] = hnew[1];
    __syncthreads();
    int w = t >> 5, lane = t & 31;
    if (w < 2) {
        float s1 = 0.f, s2 = 0.f;
        #pragma unroll
        for (int e = 0; e < 8; e++) {
            float v = su[w][lane + e*32];
            s1 += v; s2 += v*v;
        }
        #pragma unroll
        for (int o = 16; o; o >>= 1) {
            s1 += __shfl_xor_sync(0xffffffffu, s1, o);
            s2 += __shfl_xor_sync(0xffffffffu, s2, o);
        }
        if (lane == 0) {
            float m = s1 * (1.f/256.f);
            sm[w] = m;
            sr2[w] = rsqrtf(s2 * (1.f/256.f) - m*m + EPS);
        }
    }
    __syncthreads();
    float gt = lng[t], bt = lnb[t];
    sa[0][t] = (hnew[0] - sm[0]) * sr2[0] * gt + bt;
    sa[1][t] = (hnew[1] - sm[1]) * sr2[1] * gt + bt;
    __syncthreads();

    float a1[2] = {b1[t], b1[t]};
    float a2[2] = {b1[256+t], b1[256+t]};
    const float* w1a = w1 + (size_t)t*256;
    const float* w1b = w1 + (size_t)(256+t)*256;
    #pragma unroll 2
    for (int e = 0; e < 256; e += 4) {
        float4 wa = *(const float4*)&w1a[e];
        float4 wb = *(const float4*)&w1b[e];
        #pragma unroll
        for (int sl = 0; sl < 2; sl++) {
            float4 s4 = *(const float4*)&sa[sl][e];
            a1[sl] += wa.x*s4.x + wa.y*s4.y + wa.z*s4.z + wa.w*s4.w;
            a2[sl] += wb.x*s4.x + wb.y*s4.y + wb.z*s4.z + wb.w*s4.w;
        }
    }
    sh1[0][t] = fmaxf(a1[0], 0.f); sh1[0][256+t] = fmaxf(a2[0], 0.f);
    sh1[1][t] = fmaxf(a1[1], 0.f); sh1[1][256+t] = fmaxf(a2[1], 0.f);
    __syncthreads();

    float o[2] = {b2[t], b2[t]};
    const float* w2r = w2 + (size_t)t*512;
    #pragma unroll 2
    for (int e = 0; e < 512; e += 4) {
        float4 w4 = *(const float4*)&w2r[e];
        #pragma unroll
        for (int sl = 0; sl < 2; sl++) {
            float4 h4 = *(const float4*)&sh1[sl][e];
            o[sl] += w4.x*h4.x + w4.y*h4.y + w4.z*h4.z + w4.w*h4.w;
        }
    }
    #pragma unroll
    for (int sl = 0; sl < 2; sl++) {
        float res = hnew[sl] + o[sl];
        g_slots[(row0+sl)*256 + t] = res;
        if (out_slots) out_slots[(row0+sl)*256 + t] = res;
    }
}

// ---------------- K8: final attn normalize to d_out -------------------------
__global__ void k_attn_out(float* __restrict__ dst) {
    int i = blockIdx.x*blockDim.x + threadIdx.x;
    if (i < TOK*S_) {
        int s = i & 7;
        int b = i >> 15;
        dst[i] = g_attn[i] / g_cs[b*8 + s];
    }
}

// ---------------- host ------------------------------------------------------
extern "C" void kernel_launch(void* const* d_in, const int* in_sizes, int n_in,
                              void* d_out, int out_size) {
    const float* inputs     = (const float*)d_in[0];
    const float* init_noise = (const float*)d_in[1];
    const float* mu         = (const float*)d_in[2];
    const float* sigma_raw  = (const float*)d_in[3];
    const float* ln_in_g    = (const float*)d_in[4];
    const float* ln_in_b    = (const float*)d_in[5];
    const float* ln_s_g     = (const float*)d_in[6];
    const float* ln_s_b     = (const float*)d_in[7];
    const float* ln_m_g     = (const float*)d_in[8];
    const float* ln_m_b     = (const float*)d_in[9];
    const float* wq         = (const float*)d_in[10];
    const float* bq         = (const float*)d_in[11];
    const float* wk         = (const float*)d_in[12];
    const float* bk         = (const float*)d_in[13];
    const float* wv         = (const float*)d_in[14];
    const float* bv         = (const float*)d_in[15];
    const float* w_ih       = (const float*)d_in[16];
    const float* w_hh       = (const float*)d_in[17];
    const float* b_ih       = (const float*)d_in[18];
    const float* b_hh       = (const float*)d_in[19];
    const float* w1         = (const float*)d_in[20];
    const float* b1         = (const float*)d_in[21];
    const float* w2         = (const float*)d_in[22];
    const float* b2         = (const float*)d_in[23];
    float* out = (float*)d_out;

    k_prep_t<<<dim3(8,8), dim3(32,8)>>>(wk, ln_in_g);
    k_prep_b<<<1, 256>>>(wk, ln_in_b, bk);
    k_meanvar<<<TOK/8, 256>>>(inputs);
    k_init_slots<<<(B_*S_*D_ + 255)/256, 256>>>(init_noise, mu, sigma_raw);

    for (int it = 0; it < 3; ++it) {
        bool last = (it == 2);
        k_qproj3<<<B_, 256>>>(ln_s_g, ln_s_b, wq, bq);
        k_attn_fused<<<dim3(16, B_), 256>>>(inputs);
        k_gru3<<<B_*4, 256>>>(ln_in_g, ln_in_b, wv, bv,
                              w_ih, w_hh, b_ih, b_hh, ln_m_g, ln_m_b,
                              w1, b1, w2, b2, last ? out : nullptr);
        if (last) k_attn_out<<<(TOK*S_ + 255)/256, 256>>>(out + B_*S_*D_);
    }
}

// round 7
// speedup vs baseline: 3.4647x; 1.2931x over previous
#include <cuda_runtime.h>
#include <cstdint>
#include <math.h>

#define B_   32
#define N_   4096
#define D_   256
#define S_   8
#define H_   512
#define TOK  (B_*N_)      // 131072
#define EPS  1e-5f
#define SCALE 0.0625f     // 256^-0.5

// ---------------- scratch (device globals; no runtime allocation) ----------
__device__ float g_mean[TOK];
__device__ float g_rstd[TOK];
__device__ float g_slots[B_*S_*D_];
__device__ float g_p[B_*S_*D_];      // pg = scale * g ∘ (q @ wk)
__device__ float g_S1[B_*S_];
__device__ float g_S2[B_*S_];
__device__ float g_attn[TOK*S_];     // softmax + 1e-8, pre-renorm (last iter only)
__device__ float g_cs[B_*S_];        // colsum
__device__ float g_t1[B_*S_];        // sum a*r*m
__device__ float g_U[B_*S_*D_];      // sum_n a*r*x[n]
__device__ float g_wkgT[D_*D_];      // wkgT[d][j] = ln_in_g[d]*wk[j][d]
__device__ float g_wkb[D_];          // wk @ ln_in_b + bk

__device__ __forceinline__ float sigmoidf_(float x) { return 1.f / (1.f + expf(-x)); }

// ---------------- prep (merged): transposed g-scaled wk + wkb ---------------
__global__ void k_prep_all(const float* __restrict__ wk, const float* __restrict__ lng,
                           const float* __restrict__ lnb, const float* __restrict__ bk) {
    if (blockIdx.x < 64) {
        __shared__ float tile[32][33];
        int bj = blockIdx.x & 7, bd = blockIdx.x >> 3;
        int j0 = bj * 32, d0 = bd * 32;
        int tx = threadIdx.x & 31, ty = threadIdx.x >> 5;   // (32,8)
        #pragma unroll
        for (int r = 0; r < 4; r++)
            tile[ty + 8*r][tx] = wk[(size_t)(j0 + ty + 8*r) * 256 + d0 + tx];
        __syncthreads();
        #pragma unroll
        for (int r = 0; r < 4; r++) {
            int d = d0 + ty + 8*r;
            g_wkgT[(size_t)d * 256 + j0 + tx] = lng[d] * tile[tx][ty + 8*r];
        }
    } else {
        int j = threadIdx.x;
        const float* wr = wk + (size_t)j * 256;
        float acc = bk[j];
        #pragma unroll 4
        for (int e = 0; e < 256; e += 4) {
            float4 w4 = *(const float4*)&wr[e];
            float4 b4 = *(const float4*)&lnb[e];
            acc += w4.x*b4.x + w4.y*b4.y + w4.z*b4.z + w4.w*b4.w;
        }
        g_wkb[j] = acc;
    }
}

// ---------------- K1: per-token mean/rstd of inputs ------------------------
__global__ void k_meanvar(const float* __restrict__ x) {
    int warp = threadIdx.x >> 5, lane = threadIdx.x & 31;
    int tok = blockIdx.x * 8 + warp;
    const float4* row = (const float4*)(x + (size_t)tok * D_);
    float4 a = row[lane*2], b = row[lane*2+1];
    float s = a.x+a.y+a.z+a.w + b.x+b.y+b.z+b.w;
    float q = a.x*a.x+a.y*a.y+a.z*a.z+a.w*a.w + b.x*b.x+b.y*b.y+b.z*b.z+b.w*b.w;
    #pragma unroll
    for (int o = 16; o; o >>= 1) {
        s += __shfl_xor_sync(0xffffffffu, s, o);
        q += __shfl_xor_sync(0xffffffffu, q, o);
    }
    if (lane == 0) {
        float m = s * (1.f/256.f);
        g_mean[tok] = m;
        g_rstd[tok] = rsqrtf(q * (1.f/256.f) - m*m + EPS);
    }
}

// ---------------- K4: per-batch q proj + pg/S1/S2 + zeroing (+slot init) ----
__global__ void __launch_bounds__(256) k_qproj3(
    const float* __restrict__ g, const float* __restrict__ bln,
    const float* __restrict__ wq, const float* __restrict__ bq,
    int init,
    const float* __restrict__ noise, const float* __restrict__ mu,
    const float* __restrict__ sigma_raw)
{
    __shared__ __align__(16) float sa[8][256];
    __shared__ __align__(16) float sq[8][256];
    __shared__ float sm[8], sr[8];
    __shared__ float red1[8][8], red2[8][8];
    int b = blockIdx.x, t = threadIdx.x;
    int w = t >> 5, lane = t & 31;

    if (init) {
        float sr_ = sigma_raw[t];
        float sp = (sr_ > 20.f) ? sr_ : log1pf(expf(sr_));
        float muv = mu[t];
        #pragma unroll
        for (int s = 0; s < 8; s++) {
            float v = muv + sp * noise[(b*8+s)*256 + t];
            sa[s][t] = v;
            g_slots[(b*8+s)*256 + t] = v;
            g_U[(b*8+s)*256 + t] = 0.f;
        }
    } else {
        #pragma unroll
        for (int s = 0; s < 8; s++) {
            g_U[(b*8+s)*256 + t] = 0.f;
            sa[s][t] = g_slots[(b*8+s)*256 + t];
        }
    }
    if (t < 8) { g_cs[b*8 + t] = 0.f; g_t1[b*8 + t] = 0.f; }
    __syncthreads();

    // stats: warp w handles slot w
    {
        float s1 = 0.f, s2 = 0.f;
        #pragma unroll
        for (int e = 0; e < 8; e++) {
            float v = sa[w][lane + e*32];
            s1 += v; s2 += v*v;
        }
        #pragma unroll
        for (int o = 16; o; o >>= 1) {
            s1 += __shfl_xor_sync(0xffffffffu, s1, o);
            s2 += __shfl_xor_sync(0xffffffffu, s2, o);
        }
        if (lane == 0) {
            float m = s1 * (1.f/256.f);
            sm[w] = m;
            sr[w] = rsqrtf(s2 * (1.f/256.f) - m*m + EPS);
        }
    }
    __syncthreads();
    float gt = g[t], bt = bln[t];
    #pragma unroll
    for (int s = 0; s < 8; s++)
        sa[s][t] = (sa[s][t] - sm[s]) * sr[s] * gt + bt;
    __syncthreads();

    // q[s][t] = sa[s]·wq[t,:] + bq[t]
    {
        float acc[8] = {0,0,0,0,0,0,0,0};
        const float* wr = wq + (size_t)t * 256;
        #pragma unroll 2
        for (int e = 0; e < 256; e += 4) {
            float4 w4 = *(const float4*)&wr[e];
            #pragma unroll
            for (int s = 0; s < 8; s++) {
                float4 a4 = *(const float4*)&sa[s][e];
                acc[s] += w4.x*a4.x + w4.y*a4.y + w4.z*a4.z + w4.w*a4.w;
            }
        }
        float bqt = bq[t];
        #pragma unroll
        for (int s = 0; s < 8; s++) sq[s][t] = acc[s] + bqt;
    }
    __syncthreads();

    // pg[s][t] = SCALE * q[s]·wkgT[t,:]; S1 = sum_t pg; S2 = SCALE * q·wkb
    float pgv[8] = {0,0,0,0,0,0,0,0};
    {
        const float* wr = g_wkgT + (size_t)t * 256;
        #pragma unroll 2
        for (int e = 0; e < 256; e += 4) {
            float4 w4 = *(const float4*)&wr[e];
            #pragma unroll
            for (int s = 0; s < 8; s++) {
                float4 q4 = *(const float4*)&sq[s][e];
                pgv[s] += w4.x*q4.x + w4.y*q4.y + w4.z*q4.z + w4.w*q4.w;
            }
        }
    }
    float wkbt = g_wkb[t];
    float p2[8];
    #pragma unroll
    for (int s = 0; s < 8; s++) {
        pgv[s] *= SCALE;
        g_p[(b*8+s)*256 + t] = pgv[s];
        p2[s] = sq[s][t] * wkbt;
    }
    #pragma unroll
    for (int s = 0; s < 8; s++) {
        float v1 = pgv[s], v2 = p2[s];
        #pragma unroll
        for (int o = 16; o; o >>= 1) {
            v1 += __shfl_xor_sync(0xffffffffu, v1, o);
            v2 += __shfl_xor_sync(0xffffffffu, v2, o);
        }
        if (lane == 0) { red1[s][w] = v1; red2[s][w] = v2; }
    }
    __syncthreads();
    if (t < 8) {
        float a1 = 0.f, a2 = 0.f;
        #pragma unroll
        for (int i = 0; i < 8; i++) { a1 += red1[t][i]; a2 += red2[t][i]; }
        g_S1[b*8 + t] = a1;
        g_S2[b*8 + t] = a2 * SCALE;
    }
}

// ---------------- K5: fused logits+softmax+U accumulation ------------------
// grid (16 chunks, 32 batches), 256 threads. Halving-tree reduction:
// after 3 keep-half rounds, lane group (l>>2)&7 holds slot (l4 l3 l2).
__global__ void __launch_bounds__(256, 2) k_attn_fused(const float* __restrict__ x,
                                                       int store_attn) {
    __shared__ __align__(16) float sA[32][8];   // a*r per token,slot
    int b = blockIdx.y, chunk = blockIdx.x;
    int t = threadIdx.x;
    int wid = t >> 5, lane = t & 31;
    int slot = (lane >> 2) & 7;                 // slot owned by this lane

    // per-lane pg fragments + per-lane slot scalars
    float pg[8][8];
    {
        const float* pb = g_p + b*S_*D_;
        #pragma unroll
        for (int s = 0; s < 8; s++) {
            float4 a = *(const float4*)&pb[s*256 + lane*8];
            float4 c = *(const float4*)&pb[s*256 + lane*8 + 4];
            pg[s][0]=a.x; pg[s][1]=a.y; pg[s][2]=a.z; pg[s][3]=a.w;
            pg[s][4]=c.x; pg[s][5]=c.y; pg[s][6]=c.z; pg[s][7]=c.w;
        }
    }
    float S1l = g_S1[b*8 + slot];
    float S2l = g_S2[b*8 + slot];

    float u[8]  = {0,0,0,0,0,0,0,0};
    float csA = 0.f, t1A = 0.f;                 // this lane's slot accumulators
    int base_tok = b*N_ + chunk*256;

    for (int sub = 0; sub < 8; sub++) {
        int sub0 = sub * 32;
        #pragma unroll
        for (int i = 0; i < 4; i++) {
            int loc = sub0 + wid*4 + i;
            int n = base_tok + loc;
            const float* xr = x + (size_t)n*256 + lane*8;
            float4 xa = *(const float4*)xr;
            float4 xb = *(const float4*)(xr + 4);
            float dt[8];
            #pragma unroll
            for (int s = 0; s < 8; s++) {
                dt[s] = xa.x*pg[s][0] + xa.y*pg[s][1] + xa.z*pg[s][2] + xa.w*pg[s][3]
                      + xb.x*pg[s][4] + xb.y*pg[s][5] + xb.z*pg[s][6] + xb.w*pg[s][7];
            }
            // ---- halving-tree reduction: 16 shfl total ----
            float e0, e1, e2, e3;
            {
                float r0 = __shfl_xor_sync(0xffffffffu, dt[0], 16);
                float r1 = __shfl_xor_sync(0xffffffffu, dt[1], 16);
                float r2 = __shfl_xor_sync(0xffffffffu, dt[2], 16);
                float r3 = __shfl_xor_sync(0xffffffffu, dt[3], 16);
                float r4 = __shfl_xor_sync(0xffffffffu, dt[4], 16);
                float r5 = __shfl_xor_sync(0xffffffffu, dt[5], 16);
                float r6 = __shfl_xor_sync(0xffffffffu, dt[6], 16);
                float r7 = __shfl_xor_sync(0xffffffffu, dt[7], 16);
                bool hi = (lane & 16) != 0;
                e0 = hi ? (dt[4]+r4) : (dt[0]+r0);
                e1 = hi ? (dt[5]+r5) : (dt[1]+r1);
                e2 = hi ? (dt[6]+r6) : (dt[2]+r2);
                e3 = hi ? (dt[7]+r7) : (dt[3]+r3);
            }
            float f0, f1;
            {
                float r0 = __shfl_xor_sync(0xffffffffu, e0, 8);
                float r1 = __shfl_xor_sync(0xffffffffu, e1, 8);
                float r2 = __shfl_xor_sync(0xffffffffu, e2, 8);
                float r3 = __shfl_xor_sync(0xffffffffu, e3, 8);
                bool hi = (lane & 8) != 0;
                f0 = hi ? (e2+r2) : (e0+r0);
                f1 = hi ? (e3+r3) : (e1+r1);
            }
            float v;
            {
                float r0 = __shfl_xor_sync(0xffffffffu, f0, 4);
                float r1 = __shfl_xor_sync(0xffffffffu, f1, 4);
                bool hi = (lane & 4) != 0;
                v = hi ? (f1+r1) : (f0+r0);
            }
            v += __shfl_xor_sync(0xffffffffu, v, 2);
            v += __shfl_xor_sync(0xffffffffu, v, 1);
            // v = full dot(x[n], pg[slot])

            float r = g_rstd[n], m = g_mean[n];
            float rm = r * m;
            float lg = r*v - rm*S1l + S2l;
            // softmax across slots (lane-groups 4 apart; bits 2,3,4)
            float mx = lg;
            mx = fmaxf(mx, __shfl_xor_sync(0xffffffffu, mx, 4));
            mx = fmaxf(mx, __shfl_xor_sync(0xffffffffu, mx, 8));
            mx = fmaxf(mx, __shfl_xor_sync(0xffffffffu, mx, 16));
            float e = expf(lg - mx);
            float sum = e;
            sum += __shfl_xor_sync(0xffffffffu, sum, 4);
            sum += __shfl_xor_sync(0xffffffffu, sum, 8);
            sum += __shfl_xor_sync(0xffffffffu, sum, 16);
            float a = e / sum + 1e-8f;
            float ar = a * r;
            csA += a;
            t1A += a * rm;
            if ((lane & 3) == 0) {
                sA[loc - sub0][slot] = ar;
                if (store_attn) g_attn[(size_t)n*8 + slot] = a;
            }
        }
        __syncthreads();
        // ---- pass 2: thread t accumulates U over 32 tokens ----
        const float* xcol = x + (size_t)(base_tok + sub0)*256 + t;
        #pragma unroll 8
        for (int i = 0; i < 32; i++) {
            float xv = xcol[(size_t)i*256];
            float4 p0 = *(const float4*)&sA[i][0];
            float4 p1 = *(const float4*)&sA[i][4];
            u[0] += p0.x*xv; u[1] += p0.y*xv; u[2] += p0.z*xv; u[3] += p0.w*xv;
            u[4] += p1.x*xv; u[5] += p1.y*xv; u[6] += p1.z*xv; u[7] += p1.w*xv;
        }
        __syncthreads();
    }

    // flush U
    #pragma unroll
    for (int s = 0; s < 8; s++)
        atomicAdd(&g_U[(b*8+s)*256 + t], u[s]);
    // flush cs/t1: 4 redundant lanes per slot hold identical values
    if ((lane & 3) == 0) {
        atomicAdd(&g_cs[b*8 + slot], csA * 0.25f * 4.f * 0.25f * 0 + csA); // csA (kept simple)
        atomicAdd(&g_t1[b*8 + slot], t1A);
    }
}

// ---------------- K7: updates-from-U + GRU + LN + MLP ----------------------
__global__ void __launch_bounds__(256) k_gru3(
    const float* __restrict__ lng_in, const float* __restrict__ lnb_in,
    const float* __restrict__ wv,   const float* __restrict__ bv,
    const float* __restrict__ w_ih, const float* __restrict__ w_hh,
    const float* __restrict__ b_ih, const float* __restrict__ b_hh,
    const float* __restrict__ lng,  const float* __restrict__ lnb,
    const float* __restrict__ w1,   const float* __restrict__ b1,
    const float* __restrict__ w2,   const float* __restrict__ b2,
    float* __restrict__ out_slots)
{
    __shared__ __align__(16) float szn[2][256];
    __shared__ __align__(16) float su[2][256];
    __shared__ __align__(16) float sh[2][256];
    __shared__ __align__(16) float sa[2][256];
    __shared__ __align__(16) float sh1[2][512];
    __shared__ float sm[2], sr2[2];

    int b = blockIdx.x >> 2;
    int p = blockIdx.x & 3;
    int row0 = b*8 + p*2;
    int t = threadIdx.x;

    #pragma unroll
    for (int sl = 0; sl < 2; sl++) {
        int row = row0 + sl;
        float csv = g_cs[row], t1v = g_t1[row];
        float Ut = g_U[row*256 + t];
        szn[sl][t] = lng_in[t] * (Ut - t1v) / csv + lnb_in[t];
        sh[sl][t] = g_slots[row*256 + t];
    }
    __syncthreads();

    {
        float a0 = 0.f, a1 = 0.f;
        const float* wr = wv + (size_t)t * 256;
        #pragma unroll 2
        for (int e = 0; e < 256; e += 4) {
            float4 w4 = *(const float4*)&wr[e];
            float4 z0 = *(const float4*)&szn[0][e];
            float4 z1 = *(const float4*)&szn[1][e];
            a0 += w4.x*z0.x + w4.y*z0.y + w4.z*z0.z + w4.w*z0.w;
            a1 += w4.x*z1.x + w4.y*z1.y + w4.z*z1.z + w4.w*z1.w;
        }
        float bvt = bv[t];
        su[0][t] = a0 + bvt;
        su[1][t] = a1 + bvt;
    }
    __syncthreads();

    float xr[2], xz[2], xn[2], hr[2], hz[2], hn[2];
    #pragma unroll
    for (int sl = 0; sl < 2; sl++) {
        xr[sl] = b_ih[t]; xz[sl] = b_ih[256+t]; xn[sl] = b_ih[512+t];
        hr[sl] = b_hh[t]; hz[sl] = b_hh[256+t]; hn[sl] = b_hh[512+t];
    }
    const float* wir = w_ih + (size_t)t*256;
    const float* wiz = w_ih + (size_t)(256+t)*256;
    const float* win = w_ih + (size_t)(512+t)*256;
    const float* whr = w_hh + (size_t)t*256;
    const float* whz = w_hh + (size_t)(256+t)*256;
    const float* whn = w_hh + (size_t)(512+t)*256;

    #pragma unroll 2
    for (int e = 0; e < 256; e += 4) {
        float4 wr4 = *(const float4*)&wir[e];
        float4 wz4 = *(const float4*)&wiz[e];
        float4 wn4 = *(const float4*)&win[e];
        float4 vr4 = *(const float4*)&whr[e];
        float4 vz4 = *(const float4*)&whz[e];
        float4 vn4 = *(const float4*)&whn[e];
        #pragma unroll
        for (int sl = 0; sl < 2; sl++) {
            float4 u4 = *(const float4*)&su[sl][e];
            float4 h4 = *(const float4*)&sh[sl][e];
            xr[sl] += wr4.x*u4.x + wr4.y*u4.y + wr4.z*u4.z + wr4.w*u4.w;
            xz[sl] += wz4.x*u4.x + wz4.y*u4.y + wz4.z*u4.z + wz4.w*u4.w;
            xn[sl] += wn4.x*u4.x + wn4.y*u4.y + wn4.z*u4.z + wn4.w*u4.w;
            hr[sl] += vr4.x*h4.x + vr4.y*h4.y + vr4.z*h4.z + vr4.w*h4.w;
            hz[sl] += vz4.x*h4.x + vz4.y*h4.y + vz4.z*h4.z + vz4.w*h4.w;
            hn[sl] += vn4.x*h4.x + vn4.y*h4.y + vn4.z*h4.z + vn4.w*h4.w;
        }
    }
    float hnew[2];
    #pragma unroll
    for (int sl = 0; sl < 2; sl++) {
        float r = sigmoidf_(xr[sl] + hr[sl]);
        float z = sigmoidf_(xz[sl] + hz[sl]);
        float nn = tanhf(xn[sl] + r*hn[sl]);
        hnew[sl] = (1.f - z)*nn + z*sh[sl][t];
    }
    __syncthreads();
    su[0][t] = hnew[0]; su[1][t] = hnew[1];
    __syncthreads();
    int w = t >> 5, lane = t & 31;
    if (w < 2) {
        float s1 = 0.f, s2 = 0.f;
        #pragma unroll
        for (int e = 0; e < 8; e++) {
            float v = su[w][lane + e*32];
            s1 += v; s2 += v*v;
        }
        #pragma unroll
        for (int o = 16; o; o >>= 1) {
            s1 += __shfl_xor_sync(0xffffffffu, s1, o);
            s2 += __shfl_xor_sync(0xffffffffu, s2, o);
        }
        if (lane == 0) {
            float m = s1 * (1.f/256.f);
            sm[w] = m;
            sr2[w] = rsqrtf(s2 * (1.f/256.f) - m*m + EPS);
        }
    }
    __syncthreads();
    float gt = lng[t], bt = lnb[t];
    sa[0][t] = (hnew[0] - sm[0]) * sr2[0] * gt + bt;
    sa[1][t] = (hnew[1] - sm[1]) * sr2[1] * gt + bt;
    __syncthreads();

    float a1[2] = {b1[t], b1[t]};
    float a2[2] = {b1[256+t], b1[256+t]};
    const float* w1a = w1 + (size_t)t*256;
    const float* w1b = w1 + (size_t)(256+t)*256;
    #pragma unroll 2
    for (int e = 0; e < 256; e += 4) {
        float4 wa = *(const float4*)&w1a[e];
        float4 wb = *(const float4*)&w1b[e];
        #pragma unroll
        for (int sl = 0; sl < 2; sl++) {
            float4 s4 = *(const float4*)&sa[sl][e];
            a1[sl] += wa.x*s4.x + wa.y*s4.y + wa.z*s4.z + wa.w*s4.w;
            a2[sl] += wb.x*s4.x + wb.y*s4.y + wb.z*s4.z + wb.w*s4.w;
        }
    }
    sh1[0][t] = fmaxf(a1[0], 0.f); sh1[0][256+t] = fmaxf(a2[0], 0.f);
    sh1[1][t] = fmaxf(a1[1], 0.f); sh1[1][256+t] = fmaxf(a2[1], 0.f);
    __syncthreads();

    float o[2] = {b2[t], b2[t]};
    const float* w2r = w2 + (size_t)t*512;
    #pragma unroll 2
    for (int e = 0; e < 512; e += 4) {
        float4 w4 = *(const float4*)&w2r[e];
        #pragma unroll
        for (int sl = 0; sl < 2; sl++) {
            float4 h4 = *(const float4*)&sh1[sl][e];
            o[sl] += w4.x*h4.x + w4.y*h4.y + w4.z*h4.z + w4.w*h4.w;
        }
    }
    #pragma unroll
    for (int sl = 0; sl < 2; sl++) {
        float res = hnew[sl] + o[sl];
        g_slots[(row0+sl)*256 + t] = res;
        if (out_slots) out_slots[(row0+sl)*256 + t] = res;
    }
}

// ---------------- K8: final attn normalize to d_out -------------------------
__global__ void k_attn_out(float* __restrict__ dst) {
    int i = blockIdx.x*blockDim.x + threadIdx.x;
    if (i < TOK*S_) {
        int s = i & 7;
        int b = i >> 15;
        dst[i] = g_attn[i] / g_cs[b*8 + s];
    }
}

// ---------------- host ------------------------------------------------------
extern "C" void kernel_launch(void* const* d_in, const int* in_sizes, int n_in,
                              void* d_out, int out_size) {
    const float* inputs     = (const float*)d_in[0];
    const float* init_noise = (const float*)d_in[1];
    const float* mu         = (const float*)d_in[2];
    const float* sigma_raw  = (const float*)d_in[3];
    const float* ln_in_g    = (const float*)d_in[4];
    const float* ln_in_b    = (const float*)d_in[5];
    const float* ln_s_g     = (const float*)d_in[6];
    const float* ln_s_b     = (const float*)d_in[7];
    const float* ln_m_g     = (const float*)d_in[8];
    const float* ln_m_b     = (const float*)d_in[9];
    const float* wq         = (const float*)d_in[10];
    const float* bq         = (const float*)d_in[11];
    const float* wk         = (const float*)d_in[12];
    const float* bk         = (const float*)d_in[13];
    const float* wv         = (const float*)d_in[14];
    const float* bv         = (const float*)d_in[15];
    const float* w_ih       = (const float*)d_in[16];
    const float* w_hh       = (const float*)d_in[17];
    const float* b_ih       = (const float*)d_in[18];
    const float* b_hh       = (const float*)d_in[19];
    const float* w1         = (const float*)d_in[20];
    const float* b1         = (const float*)d_in[21];
    const float* w2         = (const float*)d_in[22];
    const float* b2         = (const float*)d_in[23];
    float* out = (float*)d_out;

    k_prep_all<<<65, 256>>>(wk, ln_in_g, ln_in_b, bk);
    k_meanvar<<<TOK/8, 256>>>(inputs);

    for (int it = 0; it < 3; ++it) {
        bool last = (it == 2);
        k_qproj3<<<B_, 256>>>(ln_s_g, ln_s_b, wq, bq,
                              it == 0 ? 1 : 0, init_noise, mu, sigma_raw);
        k_attn_fused<<<dim3(16, B_), 256>>>(inputs, last ? 1 : 0);
        k_gru3<<<B_*4, 256>>>(ln_in_g, ln_in_b, wv, bv,
                              w_ih, w_hh, b_ih, b_hh, ln_m_g, ln_m_b,
                              w1, b1, w2, b2, last ? out : nullptr);
        if (last) k_attn_out<<<(TOK*S_ + 255)/256, 256>>>(out + B_*S_*D_);
    }
}